// round 1
// baseline (speedup 1.0000x reference)
#include <cuda_runtime.h>
#include <math.h>

#define Bb   2048
#define Nn   64
#define Hh   256
#define MTOT (Bb*Nn)          // 131072

// ---------------- scratch (static device globals; no allocations) ----------
__device__ float g_h   [Bb*Nn*Hh];        // current hidden
__device__ float g_hn  [Bb*Nn*Hh];        // hidden after GRU cell
__device__ float g_hio [Bb*Nn*2*Hh];      // [hin | hout]
__device__ float g_inp [Bb*Nn*2*Hh];      // [inp_in | inp_out]
__device__ float g_star[Bb*Hh];
__device__ float g_Wt1 [256*512];         // k-major [k][c]: c<256 -> W_in^T, else W_out^T
__device__ float g_bias1[512];            // [b_in | b_out]
__device__ float g_Wtgi[3][512][256];     // w_ih planes: [gate][k][c]
__device__ float g_Wtgh[3][256][256];     // w_hh planes

// ---------------- weight pre-transpose --------------------------------------
__global__ void setup_weights(const float* __restrict__ W_in,
                              const float* __restrict__ b_in,
                              const float* __restrict__ W_out,
                              const float* __restrict__ b_out,
                              const float* __restrict__ w_ih,
                              const float* __restrict__ w_hh) {
    int i = blockIdx.x * blockDim.x + threadIdx.x;
    if (i < 256*512) {
        int k = i >> 9, c = i & 511;
        g_Wt1[i] = (c < 256) ? W_in[c*256 + k] : W_out[(c-256)*256 + k];
    }
    if (i < 512) g_bias1[i] = (i < 256) ? b_in[i] : b_out[i-256];
    if (i < 3*512*256) {
        int g = i / (512*256); int r = i - g*512*256;
        int k = r >> 8, c = r & 255;
        g_Wtgi[g][k][c] = w_ih[(g*256 + c)*512 + k];
    }
    if (i < 3*256*256) {
        int g = i / (256*256); int r = i - g*256*256;
        int k = r >> 8, c = r & 255;
        g_Wtgh[g][k][c] = w_hh[(g*256 + c)*256 + k];
    }
}

// ---------------- init -------------------------------------------------------
__global__ void copy_h(const float* __restrict__ src) {
    size_t n4 = (size_t)Bb*Nn*Hh/4;
    for (size_t i = blockIdx.x*(size_t)blockDim.x + threadIdx.x; i < n4;
         i += (size_t)gridDim.x*blockDim.x)
        ((float4*)g_h)[i] = ((const float4*)src)[i];
}

__global__ void star_init(const float* __restrict__ hidden,
                          const float* __restrict__ mask) {
    int b = blockIdx.x, t = threadIdx.x;
    float len = 0.f;
#pragma unroll 8
    for (int n = 0; n < 64; n++) len += mask[b*64 + n];
    float acc = 0.f;
    for (int n = 0; n < 64; n++)
        acc += hidden[((size_t)b*64 + n)*256 + t] * mask[b*64 + n];
    g_star[(size_t)b*256 + t] = acc / len;
}

// ---------------- GEMM1: g_hio = g_h @ [W_in^T | W_out^T] + bias -------------
// M=131072, K=256, N=512. CTA 128x128, 256 thr, 8x8 per thread, k-tile 16.
__global__ void __launch_bounds__(256) gemm1() {
    __shared__ float Xs[16][128];
    __shared__ float Ws[16][128];
    int t = threadIdx.x;
    int m0 = blockIdx.x * 128, c0 = blockIdx.y * 128;
    int ty = t >> 4, tx = t & 15;
    float acc[8][8];
#pragma unroll
    for (int i = 0; i < 8; i++)
#pragma unroll
        for (int j = 0; j < 8; j++) acc[i][j] = 0.f;

    for (int kt = 0; kt < 256; kt += 16) {
#pragma unroll
        for (int f = 0; f < 2; f++) {
            int idx = f*256 + t; int row = idx >> 2; int kq = idx & 3;
            float4 v = *(const float4*)&g_h[(size_t)(m0+row)*256 + kt + kq*4];
            Xs[kq*4+0][row] = v.x; Xs[kq*4+1][row] = v.y;
            Xs[kq*4+2][row] = v.z; Xs[kq*4+3][row] = v.w;
        }
#pragma unroll
        for (int f = 0; f < 2; f++) {
            int idx = f*256 + t; int k = idx >> 5; int cq = idx & 31;
            *(float4*)&Ws[k][cq*4] =
                *(const float4*)&g_Wt1[(kt+k)*512 + c0 + cq*4];
        }
        __syncthreads();
#pragma unroll
        for (int k = 0; k < 16; k++) {
            float a[8], b[8];
            *(float4*)&a[0] = *(const float4*)&Xs[k][ty*8];
            *(float4*)&a[4] = *(const float4*)&Xs[k][ty*8+4];
            *(float4*)&b[0] = *(const float4*)&Ws[k][tx*8];
            *(float4*)&b[4] = *(const float4*)&Ws[k][tx*8+4];
#pragma unroll
            for (int i = 0; i < 8; i++)
#pragma unroll
                for (int j = 0; j < 8; j++) acc[i][j] += a[i]*b[j];
        }
        __syncthreads();
    }
#pragma unroll
    for (int i = 0; i < 8; i++) {
        int m = m0 + ty*8 + i;
#pragma unroll
        for (int j = 0; j < 8; j++) {
            int c = c0 + tx*8 + j;
            g_hio[(size_t)m*512 + c] = acc[i][j] + g_bias1[c];
        }
    }
}

// ---------------- GEMM2: inp = A @ hio (batched) + b_iah/b_oah ---------------
// grid (B, 8): blockIdx.y -> half(0=in,1=out) * 4 + col-quarter. K=64.
__global__ void __launch_bounds__(256) gemm2(const float* __restrict__ A,
                                             const float* __restrict__ b_iah,
                                             const float* __restrict__ b_oah) {
    int b = blockIdx.x;
    int q = blockIdx.y; int half = q >> 2; int cq = q & 3;
    __shared__ float As[64][64];   // [k][n]
    __shared__ float Hs[64][64];   // [k][j]
    int t = threadIdx.x;
#pragma unroll
    for (int f = 0; f < 4; f++) {
        int idx = f*256 + t; int r = idx >> 4; int kq = idx & 15;
        float4 v = *(const float4*)&A[(size_t)b*8192 + r*128 + half*64 + kq*4];
        As[kq*4+0][r] = v.x; As[kq*4+1][r] = v.y;
        As[kq*4+2][r] = v.z; As[kq*4+3][r] = v.w;
        float4 w = *(const float4*)&g_hio[((size_t)b*64 + r)*512 +
                                          half*256 + cq*64 + kq*4];
        *(float4*)&Hs[r][kq*4] = w;
    }
    __syncthreads();
    int ty = t >> 4, tx = t & 15;
    float acc[4][4];
#pragma unroll
    for (int i = 0; i < 4; i++)
#pragma unroll
        for (int j = 0; j < 4; j++) acc[i][j] = 0.f;
#pragma unroll 8
    for (int k = 0; k < 64; k++) {
        float a[4], bv[4];
        *(float4*)a  = *(const float4*)&As[k][ty*4];
        *(float4*)bv = *(const float4*)&Hs[k][tx*4];
#pragma unroll
        for (int i = 0; i < 4; i++)
#pragma unroll
            for (int j = 0; j < 4; j++) acc[i][j] += a[i]*bv[j];
    }
#pragma unroll
    for (int i = 0; i < 4; i++) {
        int n = ty*4 + i;
#pragma unroll
        for (int j = 0; j < 4; j++) {
            int col = cq*64 + tx*4 + j;
            float bias = half ? b_oah[col] : b_iah[col];
            g_inp[((size_t)b*64 + n)*512 + half*256 + col] = acc[i][j] + bias;
        }
    }
}

// ---------------- GEMM3: gates + fused GRU -----------------------------------
// out tile 64 rows x 64 hidden-cols; 4 accumulators per output (r,z,i_n,h_n).
__global__ void __launch_bounds__(256) gemm3(const float* __restrict__ b_ih,
                                             const float* __restrict__ b_hh) {
    __shared__ float Is[16][64];
    __shared__ float Ws3[3][16][64];
    __shared__ float sbih[3][64], sbhh[3][64];
    int t = threadIdx.x;
    int m0 = blockIdx.x * 64, c0 = blockIdx.y * 64;
    if (t < 64) {
#pragma unroll
        for (int g = 0; g < 3; g++) {
            sbih[g][t] = b_ih[g*256 + c0 + t];
            sbhh[g][t] = b_hh[g*256 + c0 + t];
        }
    }
    int ty = t >> 4, tx = t & 15;
    float ar[4][4], az[4][4], an[4][4], ah[4][4];
#pragma unroll
    for (int i = 0; i < 4; i++)
#pragma unroll
        for (int j = 0; j < 4; j++) { ar[i][j]=0.f; az[i][j]=0.f; an[i][j]=0.f; ah[i][j]=0.f; }

    // phase 1: gi over inputs (K=512)
    for (int kt = 0; kt < 512; kt += 16) {
        {
            int row = t >> 2; int kq = t & 3;
            float4 v = *(const float4*)&g_inp[((size_t)(m0+row))*512 + kt + kq*4];
            Is[kq*4+0][row] = v.x; Is[kq*4+1][row] = v.y;
            Is[kq*4+2][row] = v.z; Is[kq*4+3][row] = v.w;
            int k2 = t >> 4; int cq = t & 15;
#pragma unroll
            for (int g = 0; g < 3; g++)
                *(float4*)&Ws3[g][k2][cq*4] =
                    *(const float4*)&g_Wtgi[g][kt+k2][c0 + cq*4];
        }
        __syncthreads();
#pragma unroll
        for (int k = 0; k < 16; k++) {
            float a[4], wr[4], wz[4], wn[4];
            *(float4*)a  = *(const float4*)&Is[k][ty*4];
            *(float4*)wr = *(const float4*)&Ws3[0][k][tx*4];
            *(float4*)wz = *(const float4*)&Ws3[1][k][tx*4];
            *(float4*)wn = *(const float4*)&Ws3[2][k][tx*4];
#pragma unroll
            for (int i = 0; i < 4; i++)
#pragma unroll
                for (int j = 0; j < 4; j++) {
                    ar[i][j] += a[i]*wr[j];
                    az[i][j] += a[i]*wz[j];
                    an[i][j] += a[i]*wn[j];
                }
        }
        __syncthreads();
    }
    // phase 2: gh over h (K=256); plane 2 kept separate (h_n)
    for (int kt = 0; kt < 256; kt += 16) {
        {
            int row = t >> 2; int kq = t & 3;
            float4 v = *(const float4*)&g_h[((size_t)(m0+row))*256 + kt + kq*4];
            Is[kq*4+0][row] = v.x; Is[kq*4+1][row] = v.y;
            Is[kq*4+2][row] = v.z; Is[kq*4+3][row] = v.w;
            int k2 = t >> 4; int cq = t & 15;
#pragma unroll
            for (int g = 0; g < 3; g++)
                *(float4*)&Ws3[g][k2][cq*4] =
                    *(const float4*)&g_Wtgh[g][kt+k2][c0 + cq*4];
        }
        __syncthreads();
#pragma unroll
        for (int k = 0; k < 16; k++) {
            float a[4], wr[4], wz[4], wn[4];
            *(float4*)a  = *(const float4*)&Is[k][ty*4];
            *(float4*)wr = *(const float4*)&Ws3[0][k][tx*4];
            *(float4*)wz = *(const float4*)&Ws3[1][k][tx*4];
            *(float4*)wn = *(const float4*)&Ws3[2][k][tx*4];
#pragma unroll
            for (int i = 0; i < 4; i++)
#pragma unroll
                for (int j = 0; j < 4; j++) {
                    ar[i][j] += a[i]*wr[j];
                    az[i][j] += a[i]*wz[j];
                    ah[i][j] += a[i]*wn[j];
                }
        }
        __syncthreads();
    }
    // GRU epilogue
#pragma unroll
    for (int i = 0; i < 4; i++) {
        int m = m0 + ty*4 + i;
#pragma unroll
        for (int j = 0; j < 4; j++) {
            int cl = tx*4 + j;
            int c  = c0 + cl;
            float r  = 1.f / (1.f + expf(-(ar[i][j] + sbih[0][cl] + sbhh[0][cl])));
            float z  = 1.f / (1.f + expf(-(az[i][j] + sbih[1][cl] + sbhh[1][cl])));
            float nn = tanhf(an[i][j] + sbih[2][cl] + r*(ah[i][j] + sbhh[2][cl]));
            float ho = g_h[(size_t)m*256 + c];
            g_hn[(size_t)m*256 + c] = nn + z*(ho - nn);
        }
    }
}

// ---------------- attention / star update ------------------------------------
__global__ void __launch_bounds__(256) attn(const float* __restrict__ mask,
                                            float* __restrict__ out,
                                            int final_) {
    int b = blockIdx.x, t = threadIdx.x, lane = t & 31, w = t >> 5;
    __shared__ float s_star[256];
    __shared__ float s_alpha[64];
    __shared__ float s_v[64];
    __shared__ float s_p[64];
    s_star[t] = g_star[(size_t)b*256 + t];
    __syncthreads();
    // sim_raw[n] = h_n . star  (8 warps x 8 rows)
#pragma unroll
    for (int r = 0; r < 8; r++) {
        int n = w*8 + r;
        const float* hr = &g_hn[((size_t)b*64 + n)*256];
        float p = 0.f;
#pragma unroll
        for (int j = lane; j < 256; j += 32) p += hr[j] * s_star[j];
#pragma unroll
        for (int o = 16; o; o >>= 1) p += __shfl_xor_sync(0xffffffffu, p, o);
        if (lane == 0) s_v[n] = p;
    }
    __syncthreads();
    float ss = 0.f;
#pragma unroll 8
    for (int j = 0; j < 256; j++) { float x = s_star[j]; ss += x*x; }
    if (t < 64) {
        float sraw = s_v[t];
        float a = 1.f / (1.f + expf(-sraw * 0.0625f));
        s_alpha[t] = a;
        // h2 . star = (1-a)*(hn.star) + a*(star.star)  (exact by linearity)
        float d2 = (1.f - a)*sraw + a*ss;
        s_v[t] = expf(d2) * mask[(size_t)b*64 + t];
    }
    __syncthreads();
    float den = 1e-24f;
#pragma unroll
    for (int n = 0; n < 64; n++) den += s_v[n];
    if (t < 64) s_p[t] = s_v[t] / den;
    __syncthreads();
    float st = s_star[t];
    float accS = 0.f;
#pragma unroll 4
    for (int n = 0; n < 64; n++) {
        float a = s_alpha[n];
        size_t idx = ((size_t)b*64 + n)*256 + t;
        float h2 = (1.f - a)*g_hn[idx] + a*st;
        g_h[idx] = h2;
        if (final_) out[idx] = h2;
        accS += s_p[n] * h2;
    }
    g_star[(size_t)b*256 + t] = accS;
    if (final_) out[(size_t)Bb*Nn*Hh + (size_t)b*256 + t] = accS;
}

// ---------------- launch ------------------------------------------------------
extern "C" void kernel_launch(void* const* d_in, const int* in_sizes, int n_in,
                              void* d_out, int out_size) {
    const float* A      = (const float*)d_in[0];
    const float* hidden = (const float*)d_in[1];
    const float* mask   = (const float*)d_in[2];
    const float* w_ih   = (const float*)d_in[3];
    const float* w_hh   = (const float*)d_in[4];
    const float* b_ih   = (const float*)d_in[5];
    const float* b_hh   = (const float*)d_in[6];
    const float* b_iah  = (const float*)d_in[7];
    const float* b_oah  = (const float*)d_in[8];
    const float* W_in   = (const float*)d_in[9];
    const float* b_in   = (const float*)d_in[10];
    const float* W_out  = (const float*)d_in[11];
    const float* b_out  = (const float*)d_in[12];
    float* out = (float*)d_out;

    setup_weights<<<1536, 256>>>(W_in, b_in, W_out, b_out, w_ih, w_hh);
    copy_h<<<4096, 256>>>(hidden);
    star_init<<<Bb, 256>>>(hidden, mask);

    for (int s = 0; s < 2; s++) {
        gemm1<<<dim3(MTOT/128, 4), 256>>>();
        gemm2<<<dim3(Bb, 8), 256>>>(A, b_iah, b_oah);
        gemm3<<<dim3(MTOT/64, 4), 256>>>(b_ih, b_hh);
        attn<<<Bb, 256>>>(mask, out, s == 1);
    }
}

// round 3
// speedup vs baseline: 1.4921x; 1.4921x over previous
#include <cuda_runtime.h>
#include <cuda_bf16.h>
#include <math.h>
#include <cstdint>

#define Bb   2048
#define Nn   64
#define Hh   256
#define MTOT (Bb*Nn)          // 131072

// ---------------- scratch (static device globals; no allocations) ----------
__device__ float g_h   [MTOT*Hh];         // current hidden (fp32)
__device__ float g_hn  [MTOT*Hh];         // hidden after GRU cell
__device__ float g_hio [MTOT*2*Hh];       // [hin | hout] fp32
__device__ float g_star[Bb*Hh];
__device__ float g_Wt1 [256*512];         // k-major [k][c]
__device__ float g_bias1[512];
// bf16 hi/lo split operands for tensor-core gemm3
__device__ __nv_bfloat16 g_inpH[MTOT*512];
__device__ __nv_bfloat16 g_inpL[MTOT*512];
__device__ __nv_bfloat16 g_hH  [MTOT*256];
__device__ __nv_bfloat16 g_hL  [MTOT*256];
__device__ __nv_bfloat16 g_wihH[768*512];
__device__ __nv_bfloat16 g_wihL[768*512];
__device__ __nv_bfloat16 g_whhH[768*256];
__device__ __nv_bfloat16 g_whhL[768*256];

// ---------------- helpers ----------------------------------------------------
__device__ __forceinline__ uint32_t smem_u32(const void* p) {
    uint32_t a;
    asm("{ .reg .u64 t; cvta.to.shared.u64 t, %1; cvt.u32.u64 %0, t; }"
        : "=r"(a) : "l"(p));
    return a;
}
__device__ __forceinline__ void cp16(uint32_t dst, const void* src) {
    asm volatile("cp.async.cg.shared.global [%0], [%1], 16;"
                 :: "r"(dst), "l"(src) : "memory");
}
#define CP_COMMIT() asm volatile("cp.async.commit_group;" ::: "memory")
#define CP_WAIT(n)  asm volatile("cp.async.wait_group %0;" :: "n"(n) : "memory")

__device__ __forceinline__ void ldsm_x4(uint32_t& r0, uint32_t& r1,
                                        uint32_t& r2, uint32_t& r3,
                                        uint32_t addr) {
    asm volatile("ldmatrix.sync.aligned.m8n8.x4.shared.b16 {%0,%1,%2,%3}, [%4];"
                 : "=r"(r0), "=r"(r1), "=r"(r2), "=r"(r3) : "r"(addr));
}
__device__ __forceinline__ void mma_bf16(float* d,
                                         uint32_t a0, uint32_t a1,
                                         uint32_t a2, uint32_t a3,
                                         uint32_t b0, uint32_t b1) {
    asm volatile(
        "mma.sync.aligned.m16n8k16.row.col.f32.bf16.bf16.f32 "
        "{%0,%1,%2,%3}, {%4,%5,%6,%7}, {%8,%9}, {%0,%1,%2,%3};"
        : "+f"(d[0]), "+f"(d[1]), "+f"(d[2]), "+f"(d[3])
        : "r"(a0), "r"(a1), "r"(a2), "r"(a3), "r"(b0), "r"(b1));
}
__device__ __forceinline__ void bf_split(float v, __nv_bfloat16& hi, __nv_bfloat16& lo) {
    hi = __float2bfloat16(v);
    lo = __float2bfloat16(v - __bfloat162float(hi));
}

// ---------------- weight prep -----------------------------------------------
__global__ void setup_weights(const float* __restrict__ W_in,
                              const float* __restrict__ b_in,
                              const float* __restrict__ W_out,
                              const float* __restrict__ b_out,
                              const float* __restrict__ w_ih,
                              const float* __restrict__ w_hh) {
    int i = blockIdx.x * blockDim.x + threadIdx.x;
    if (i < 256*512) {
        int k = i >> 9, c = i & 511;
        g_Wt1[i] = (c < 256) ? W_in[c*256 + k] : W_out[(c-256)*256 + k];
    }
    if (i < 512) g_bias1[i] = (i < 256) ? b_in[i] : b_out[i-256];
    if (i < 768*512) {                // w_ih already [N=768, K=512] k-major
        __nv_bfloat16 hi, lo; bf_split(w_ih[i], hi, lo);
        g_wihH[i] = hi; g_wihL[i] = lo;
    }
    if (i < 768*256) {
        __nv_bfloat16 hi, lo; bf_split(w_hh[i], hi, lo);
        g_whhH[i] = hi; g_whhL[i] = lo;
    }
}

// ---------------- init -------------------------------------------------------
__global__ void copy_h(const float* __restrict__ src) {
    size_t n = (size_t)MTOT*256;
    for (size_t i = blockIdx.x*(size_t)blockDim.x + threadIdx.x; i < n;
         i += (size_t)gridDim.x*blockDim.x) {
        float v = src[i];
        g_h[i] = v;
        __nv_bfloat16 hi, lo; bf_split(v, hi, lo);
        g_hH[i] = hi; g_hL[i] = lo;
    }
}

__global__ void star_init(const float* __restrict__ hidden,
                          const float* __restrict__ mask) {
    int b = blockIdx.x, t = threadIdx.x;
    float len = 0.f;
#pragma unroll 8
    for (int n = 0; n < 64; n++) len += mask[b*64 + n];
    float acc = 0.f;
    for (int n = 0; n < 64; n++)
        acc += hidden[((size_t)b*64 + n)*256 + t] * mask[b*64 + n];
    g_star[(size_t)b*256 + t] = acc / len;
}

// ---------------- GEMM1: g_hio = g_h @ [W_in^T | W_out^T] + bias (fp32) -----
__global__ void __launch_bounds__(256) gemm1() {
    __shared__ float Xs[16][128];
    __shared__ float Ws[16][128];
    int t = threadIdx.x;
    int m0 = blockIdx.x * 128, c0 = blockIdx.y * 128;
    int ty = t >> 4, tx = t & 15;
    float acc[8][8];
#pragma unroll
    for (int i = 0; i < 8; i++)
#pragma unroll
        for (int j = 0; j < 8; j++) acc[i][j] = 0.f;

    for (int kt = 0; kt < 256; kt += 16) {
#pragma unroll
        for (int f = 0; f < 2; f++) {
            int idx = f*256 + t; int row = idx >> 2; int kq = idx & 3;
            float4 v = *(const float4*)&g_h[(size_t)(m0+row)*256 + kt + kq*4];
            Xs[kq*4+0][row] = v.x; Xs[kq*4+1][row] = v.y;
            Xs[kq*4+2][row] = v.z; Xs[kq*4+3][row] = v.w;
        }
#pragma unroll
        for (int f = 0; f < 2; f++) {
            int idx = f*256 + t; int k = idx >> 5; int cq = idx & 31;
            *(float4*)&Ws[k][cq*4] =
                *(const float4*)&g_Wt1[(kt+k)*512 + c0 + cq*4];
        }
        __syncthreads();
#pragma unroll
        for (int k = 0; k < 16; k++) {
            float a[8], b[8];
            *(float4*)&a[0] = *(const float4*)&Xs[k][ty*8];
            *(float4*)&a[4] = *(const float4*)&Xs[k][ty*8+4];
            *(float4*)&b[0] = *(const float4*)&Ws[k][tx*8];
            *(float4*)&b[4] = *(const float4*)&Ws[k][tx*8+4];
#pragma unroll
            for (int i = 0; i < 8; i++)
#pragma unroll
                for (int j = 0; j < 8; j++) acc[i][j] += a[i]*b[j];
        }
        __syncthreads();
    }
#pragma unroll
    for (int i = 0; i < 8; i++) {
        int m = m0 + ty*8 + i;
#pragma unroll
        for (int j = 0; j < 8; j++) {
            int c = c0 + tx*8 + j;
            g_hio[(size_t)m*512 + c] = acc[i][j] + g_bias1[c];
        }
    }
}

// ---------------- GEMM2: inp = A @ hio + bias -> bf16 hi/lo -------------------
__global__ void __launch_bounds__(256) gemm2(const float* __restrict__ A,
                                             const float* __restrict__ b_iah,
                                             const float* __restrict__ b_oah) {
    int b = blockIdx.x;
    int q = blockIdx.y; int half = q >> 2; int cq = q & 3;
    __shared__ float As[64][64];
    __shared__ float Hs[64][64];
    int t = threadIdx.x;
#pragma unroll
    for (int f = 0; f < 4; f++) {
        int idx = f*256 + t; int r = idx >> 4; int kq = idx & 15;
        float4 v = *(const float4*)&A[(size_t)b*8192 + r*128 + half*64 + kq*4];
        As[kq*4+0][r] = v.x; As[kq*4+1][r] = v.y;
        As[kq*4+2][r] = v.z; As[kq*4+3][r] = v.w;
        float4 w = *(const float4*)&g_hio[((size_t)b*64 + r)*512 +
                                          half*256 + cq*64 + kq*4];
        *(float4*)&Hs[r][kq*4] = w;
    }
    __syncthreads();
    int ty = t >> 4, tx = t & 15;
    float acc[4][4];
#pragma unroll
    for (int i = 0; i < 4; i++)
#pragma unroll
        for (int j = 0; j < 4; j++) acc[i][j] = 0.f;
#pragma unroll 8
    for (int k = 0; k < 64; k++) {
        float a[4], bv[4];
        *(float4*)a  = *(const float4*)&As[k][ty*4];
        *(float4*)bv = *(const float4*)&Hs[k][tx*4];
#pragma unroll
        for (int i = 0; i < 4; i++)
#pragma unroll
            for (int j = 0; j < 4; j++) acc[i][j] += a[i]*bv[j];
    }
#pragma unroll
    for (int i = 0; i < 4; i++) {
        int n = ty*4 + i;
#pragma unroll
        for (int j = 0; j < 4; j++) {
            int col = cq*64 + tx*4 + j;
            float bias = half ? b_oah[col] : b_iah[col];
            float v = acc[i][j] + bias;
            size_t o = ((size_t)b*64 + n)*512 + half*256 + col;
            __nv_bfloat16 hi, lo; bf_split(v, hi, lo);
            g_inpH[o] = hi; g_inpL[o] = lo;
        }
    }
}

// ---------------- GEMM3: HMMA (mma.sync bf16x3) gates + fused GRU -------------
// CTA: 128 rows x 64 hidden cols x 4 planes (r,z,i_n,h_n). 8 warps, 16 rows each.
// 12 K-chunks of 64: 0..7 = inputs (K=512, w_ih), 8..11 = h (K=256, w_hh).
// SMEM stage (bytes): A_hi[128][72h]@0, A_lo@18432, B_hi[192][72h]@36864, B_lo@64512
#define G3_STAGE 92160
#define G3_BIAS  (2*G3_STAGE)                 // 184320
#define G3_SMEM  (G3_BIAS + 1536)

__device__ __forceinline__ void g3_load(uint32_t sbase, int st, int ch,
                                        int m0, int c0) {
    const int t = threadIdx.x;
    uint32_t sb = sbase + st*G3_STAGE;
    const __nv_bfloat16 *Ah, *Al, *Bh, *Bl; int ak, koff;
    if (ch < 8) { Ah=g_inpH; Al=g_inpL; Bh=g_wihH; Bl=g_wihL; ak=512; koff=ch*64; }
    else        { Ah=g_hH;   Al=g_hL;   Bh=g_whhH; Bl=g_whhL; ak=256; koff=(ch-8)*64; }
#pragma unroll
    for (int f = 0; f < 4; f++) {
        int u = f*256 + t; int row = u >> 3, seg = u & 7;
        size_t so = (size_t)(m0+row)*ak + koff + seg*8;
        uint32_t d = sb + row*144 + seg*16;
        cp16(d,         Ah + so);
        cp16(d + 18432, Al + so);
    }
#pragma unroll
    for (int f = 0; f < 6; f++) {
        int u = f*256 + t; int row = u >> 3, seg = u & 7;
        int g = row >> 6, n = row & 63;
        size_t so = (size_t)(g*256 + c0 + n)*ak + koff + seg*8;
        uint32_t d = sb + 36864 + row*144 + seg*16;
        cp16(d,         Bh + so);
        cp16(d + 27648, Bl + so);
    }
}

template<bool GH>
__device__ __forceinline__ void g3_mma_chunk(uint32_t sb, int wid, int lane,
                                             float (&acc)[4][8][4]) {
    uint32_t aRow = sb + (wid*16 + (lane & 15))*144 + (lane >> 4)*16;
    const int midx = lane >> 3;
    const int trow = (midx >> 1)*8 + (lane & 7);   // row-within-pair for B x4
    const int kh   = (midx & 1)*16;                // bytes
#pragma unroll
    for (int s = 0; s < 3; s++) {
        const int sa = (s == 2) ? 1 : 0;
        const int sbl = (s == 1) ? 1 : 0;
#pragma unroll
        for (int kt = 0; kt < 4; kt++) {
            uint32_t a0, a1, a2, a3;
            ldsm_x4(a0, a1, a2, a3, aRow + sa*18432 + kt*32);
#pragma unroll
            for (int g = 0; g < 3; g++) {
                const int p = (!GH || g < 2) ? g : 3;
#pragma unroll
                for (int jj = 0; jj < 4; jj++) {
                    uint32_t ba = sb + 36864 + sbl*27648 +
                                  (g*64 + jj*16 + trow)*144 + kt*32 + kh;
                    uint32_t b0, b1, b2, b3;
                    ldsm_x4(b0, b1, b2, b3, ba);
                    mma_bf16(acc[p][2*jj],   a0, a1, a2, a3, b0, b1);
                    mma_bf16(acc[p][2*jj+1], a0, a1, a2, a3, b2, b3);
                }
            }
        }
    }
}

__global__ void __launch_bounds__(256) gemm3_mma(const float* __restrict__ b_ih,
                                                 const float* __restrict__ b_hh) {
    extern __shared__ __align__(16) char smem[];
    const int t = threadIdx.x, wid = t >> 5, lane = t & 31;
    const int c0 = blockIdx.x * 64, m0 = blockIdx.y * 128;
    uint32_t sbase = smem_u32(smem);
    float* sbih = (float*)(smem + G3_BIAS);
    float* sbhh = (float*)(smem + G3_BIAS + 768);
    if (t < 64) {
#pragma unroll
        for (int g = 0; g < 3; g++) {
            sbih[g*64 + t] = b_ih[g*256 + c0 + t];
            sbhh[g*64 + t] = b_hh[g*256 + c0 + t];
        }
    }
    float acc[4][8][4];
#pragma unroll
    for (int p = 0; p < 4; p++)
#pragma unroll
        for (int j = 0; j < 8; j++)
#pragma unroll
            for (int i = 0; i < 4; i++) acc[p][j][i] = 0.f;

    g3_load(sbase, 0, 0, m0, c0);
    CP_COMMIT();

    for (int ch = 0; ch < 12; ch++) {
        if (ch + 1 < 12) {
            g3_load(sbase, (ch + 1) & 1, ch + 1, m0, c0);
            CP_COMMIT();
            CP_WAIT(1);
        } else {
            CP_WAIT(0);
        }
        __syncthreads();
        uint32_t sb = sbase + (ch & 1)*G3_STAGE;
        if (ch < 8) g3_mma_chunk<false>(sb, wid, lane, acc);
        else        g3_mma_chunk<true >(sb, wid, lane, acc);
        __syncthreads();
    }

    // GRU epilogue. Fragment: d0=(r,c) d1=(r,c+1) d2=(r+8,c) d3=(r+8,c+1)
    const int r0 = m0 + wid*16 + (lane >> 2);
    const int cb = (lane & 3)*2;
#pragma unroll
    for (int j = 0; j < 8; j++) {
        int c = c0 + j*8 + cb;
#pragma unroll
        for (int hrow = 0; hrow < 2; hrow++) {
            int m = r0 + hrow*8;
            float2 ho = *(const float2*)&g_h[(size_t)m*256 + c];
            float o[2];
#pragma unroll
            for (int e = 0; e < 2; e++) {
                int cl = j*8 + cb + e;
                int fi = hrow*2 + e;
                float r = 1.f/(1.f + expf(-(acc[0][j][fi] + sbih[cl] + sbhh[cl])));
                float z = 1.f/(1.f + expf(-(acc[1][j][fi] + sbih[64+cl] + sbhh[64+cl])));
                float nn = tanhf(acc[2][j][fi] + sbih[128+cl] +
                                 r*(acc[3][j][fi] + sbhh[128+cl]));
                float hv = e ? ho.y : ho.x;
                o[e] = nn + z*(hv - nn);
            }
            *(float2*)&g_hn[(size_t)m*256 + c] = make_float2(o[0], o[1]);
        }
    }
}

// ---------------- attention / star update ------------------------------------
__global__ void __launch_bounds__(256) attn(const float* __restrict__ mask,
                                            float* __restrict__ out,
                                            int final_) {
    int b = blockIdx.x, t = threadIdx.x, lane = t & 31, w = t >> 5;
    __shared__ float s_star[256];
    __shared__ float s_alpha[64];
    __shared__ float s_v[64];
    __shared__ float s_p[64];
    s_star[t] = g_star[(size_t)b*256 + t];
    __syncthreads();
#pragma unroll
    for (int r = 0; r < 8; r++) {
        int n = w*8 + r;
        const float* hr = &g_hn[((size_t)b*64 + n)*256];
        float p = 0.f;
#pragma unroll
        for (int j = lane; j < 256; j += 32) p += hr[j] * s_star[j];
#pragma unroll
        for (int o = 16; o; o >>= 1) p += __shfl_xor_sync(0xffffffffu, p, o);
        if (lane == 0) s_v[n] = p;
    }
    __syncthreads();
    float ss = 0.f;
#pragma unroll 8
    for (int j = 0; j < 256; j++) { float x = s_star[j]; ss += x*x; }
    if (t < 64) {
        float sraw = s_v[t];
        float a = 1.f / (1.f + expf(-sraw * 0.0625f));
        s_alpha[t] = a;
        float d2 = (1.f - a)*sraw + a*ss;
        s_v[t] = expf(d2) * mask[(size_t)b*64 + t];
    }
    __syncthreads();
    float den = 1e-24f;
#pragma unroll
    for (int n = 0; n < 64; n++) den += s_v[n];
    if (t < 64) s_p[t] = s_v[t] / den;
    __syncthreads();
    float st = s_star[t];
    float accS = 0.f;
#pragma unroll 4
    for (int n = 0; n < 64; n++) {
        float a = s_alpha[n];
        size_t idx = ((size_t)b*64 + n)*256 + t;
        float h2 = (1.f - a)*g_hn[idx] + a*st;
        g_h[idx] = h2;
        __nv_bfloat16 hi, lo; bf_split(h2, hi, lo);
        g_hH[idx] = hi; g_hL[idx] = lo;
        if (final_) out[idx] = h2;
        accS += s_p[n] * h2;
    }
    g_star[(size_t)b*256 + t] = accS;
    if (final_) out[(size_t)Bb*Nn*Hh + (size_t)b*256 + t] = accS;
}

// ---------------- launch ------------------------------------------------------
extern "C" void kernel_launch(void* const* d_in, const int* in_sizes, int n_in,
                              void* d_out, int out_size) {
    const float* A      = (const float*)d_in[0];
    const float* hidden = (const float*)d_in[1];
    const float* mask   = (const float*)d_in[2];
    const float* w_ih   = (const float*)d_in[3];
    const float* w_hh   = (const float*)d_in[4];
    const float* b_ih   = (const float*)d_in[5];
    const float* b_hh   = (const float*)d_in[6];
    const float* b_iah  = (const float*)d_in[7];
    const float* b_oah  = (const float*)d_in[8];
    const float* W_in   = (const float*)d_in[9];
    const float* b_in   = (const float*)d_in[10];
    const float* W_out  = (const float*)d_in[11];
    const float* b_out  = (const float*)d_in[12];
    float* out = (float*)d_out;

    cudaFuncSetAttribute(gemm3_mma, cudaFuncAttributeMaxDynamicSharedMemorySize,
                         G3_SMEM);

    setup_weights<<<1536, 256>>>(W_in, b_in, W_out, b_out, w_ih, w_hh);
    copy_h<<<4096, 256>>>(hidden);
    star_init<<<Bb, 256>>>(hidden, mask);

    for (int s = 0; s < 2; s++) {
        gemm1<<<dim3(MTOT/128, 4), 256>>>();
        gemm2<<<dim3(Bb, 8), 256>>>(A, b_iah, b_oah);
        gemm3_mma<<<dim3(4, MTOT/128), 256, G3_SMEM>>>(b_ih, b_hh);
        attn<<<Bb, 256>>>(mask, out, s == 1);
    }
}

// round 4
// speedup vs baseline: 1.9072x; 1.2782x over previous
#include <cuda_runtime.h>
#include <cuda_bf16.h>
#include <math.h>
#include <cstdint>

#define Bb   2048
#define Nn   64
#define Hh   256
#define MTOT (Bb*Nn)          // 131072

// ---------------- scratch (static device globals; no allocations) ----------
__device__ float g_h   [MTOT*Hh];         // current hidden (fp32)
__device__ float g_hn  [MTOT*Hh];         // hidden after GRU cell
__device__ float g_hio [MTOT*2*Hh];       // [hin | hout] fp32
__device__ float g_star[Bb*Hh];
__device__ float g_bias1[512];
// bf16 hi/lo split operands for tensor-core GEMMs
__device__ __nv_bfloat16 g_inpH[MTOT*512];
__device__ __nv_bfloat16 g_inpL[MTOT*512];
__device__ __nv_bfloat16 g_hH  [MTOT*256];
__device__ __nv_bfloat16 g_hL  [MTOT*256];
__device__ __nv_bfloat16 g_wihH[768*512];
__device__ __nv_bfloat16 g_wihL[768*512];
__device__ __nv_bfloat16 g_whhH[768*256];
__device__ __nv_bfloat16 g_whhL[768*256];
__device__ __nv_bfloat16 g_w1H [512*256];  // [c][k]: c<256 W_in, else W_out
__device__ __nv_bfloat16 g_w1L [512*256];

// ---------------- helpers ----------------------------------------------------
__device__ __forceinline__ uint32_t smem_u32(const void* p) {
    uint32_t a;
    asm("{ .reg .u64 t; cvta.to.shared.u64 t, %1; cvt.u32.u64 %0, t; }"
        : "=r"(a) : "l"(p));
    return a;
}
__device__ __forceinline__ void cp16(uint32_t dst, const void* src) {
    asm volatile("cp.async.cg.shared.global [%0], [%1], 16;"
                 :: "r"(dst), "l"(src) : "memory");
}
#define CP_COMMIT() asm volatile("cp.async.commit_group;" ::: "memory")
#define CP_WAIT(n)  asm volatile("cp.async.wait_group %0;" :: "n"(n) : "memory")

__device__ __forceinline__ void ldsm_x4(uint32_t& r0, uint32_t& r1,
                                        uint32_t& r2, uint32_t& r3,
                                        uint32_t addr) {
    asm volatile("ldmatrix.sync.aligned.m8n8.x4.shared.b16 {%0,%1,%2,%3}, [%4];"
                 : "=r"(r0), "=r"(r1), "=r"(r2), "=r"(r3) : "r"(addr));
}
__device__ __forceinline__ void mma_bf16(float* d,
                                         uint32_t a0, uint32_t a1,
                                         uint32_t a2, uint32_t a3,
                                         uint32_t b0, uint32_t b1) {
    asm volatile(
        "mma.sync.aligned.m16n8k16.row.col.f32.bf16.bf16.f32 "
        "{%0,%1,%2,%3}, {%4,%5,%6,%7}, {%8,%9}, {%0,%1,%2,%3};"
        : "+f"(d[0]), "+f"(d[1]), "+f"(d[2]), "+f"(d[3])
        : "r"(a0), "r"(a1), "r"(a2), "r"(a3), "r"(b0), "r"(b1));
}
__device__ __forceinline__ void bf_split(float v, __nv_bfloat16& hi, __nv_bfloat16& lo) {
    hi = __float2bfloat16(v);
    lo = __float2bfloat16(v - __bfloat162float(hi));
}

// ---------------- weight prep -----------------------------------------------
__global__ void setup_weights(const float* __restrict__ W_in,
                              const float* __restrict__ b_in,
                              const float* __restrict__ W_out,
                              const float* __restrict__ b_out,
                              const float* __restrict__ w_ih,
                              const float* __restrict__ w_hh) {
    int i = blockIdx.x * blockDim.x + threadIdx.x;
    if (i < 512) g_bias1[i] = (i < 256) ? b_in[i] : b_out[i-256];
    if (i < 512*256) {                // gemm1 weights, k-major
        int c = i >> 8, k = i & 255;
        float v = (c < 256) ? W_in[c*256 + k] : W_out[(c-256)*256 + k];
        __nv_bfloat16 hi, lo; bf_split(v, hi, lo);
        g_w1H[i] = hi; g_w1L[i] = lo;
    }
    if (i < 768*512) {                // w_ih already [N=768, K=512] k-major
        __nv_bfloat16 hi, lo; bf_split(w_ih[i], hi, lo);
        g_wihH[i] = hi; g_wihL[i] = lo;
    }
    if (i < 768*256) {
        __nv_bfloat16 hi, lo; bf_split(w_hh[i], hi, lo);
        g_whhH[i] = hi; g_whhL[i] = lo;
    }
}

// ---------------- init -------------------------------------------------------
__global__ void copy_h(const float* __restrict__ src) {
    size_t n = (size_t)MTOT*256;
    for (size_t i = blockIdx.x*(size_t)blockDim.x + threadIdx.x; i < n;
         i += (size_t)gridDim.x*blockDim.x) {
        float v = src[i];
        g_h[i] = v;
        __nv_bfloat16 hi, lo; bf_split(v, hi, lo);
        g_hH[i] = hi; g_hL[i] = lo;
    }
}

__global__ void star_init(const float* __restrict__ hidden,
                          const float* __restrict__ mask) {
    int b = blockIdx.x, t = threadIdx.x;
    float len = 0.f;
#pragma unroll 8
    for (int n = 0; n < 64; n++) len += mask[b*64 + n];
    float acc = 0.f;
    for (int n = 0; n < 64; n++)
        acc += hidden[((size_t)b*64 + n)*256 + t] * mask[b*64 + n];
    g_star[(size_t)b*256 + t] = acc / len;
}

// ---------------- GEMM1 (HMMA): hio = h @ [W_in^T|W_out^T] + bias ------------
// CTA: 128 rows x 64 cols, K=256 in 4 chunks of 64. 2 CTAs/SM.
#define G1_STAGE 55296
#define G1_SMEM  (2*G1_STAGE)

__device__ __forceinline__ void g1_load(uint32_t sbase, int st, int ch,
                                        int m0, int c0) {
    const int t = threadIdx.x;
    uint32_t sb = sbase + st*G1_STAGE;
    int koff = ch*64;
#pragma unroll
    for (int f = 0; f < 4; f++) {
        int u = f*256 + t; int row = u >> 3, seg = u & 7;
        size_t so = (size_t)(m0+row)*256 + koff + seg*8;
        uint32_t d = sb + row*144 + seg*16;
        cp16(d,         g_hH + so);
        cp16(d + 18432, g_hL + so);
    }
#pragma unroll
    for (int f = 0; f < 2; f++) {
        int u = f*256 + t; int row = u >> 3, seg = u & 7;
        size_t so = (size_t)(c0+row)*256 + koff + seg*8;
        uint32_t d = sb + 36864 + row*144 + seg*16;
        cp16(d,        g_w1H + so);
        cp16(d + 9216, g_w1L + so);
    }
}

__global__ void __launch_bounds__(256, 2) gemm1_mma() {
    extern __shared__ __align__(16) char smem[];
    const int t = threadIdx.x, wid = t >> 5, lane = t & 31;
    const int c0 = blockIdx.x * 64, m0 = blockIdx.y * 128;
    uint32_t sbase = smem_u32(smem);
    float acc[8][4];
#pragma unroll
    for (int j = 0; j < 8; j++)
#pragma unroll
        for (int i = 0; i < 4; i++) acc[j][i] = 0.f;

    g1_load(sbase, 0, 0, m0, c0);
    CP_COMMIT();

    const uint32_t aRow0 = (wid*16 + (lane & 15))*144 + (lane >> 4)*16;
    const int midx = lane >> 3;
    const int trow = (midx >> 1)*8 + (lane & 7);
    const int kh   = (midx & 1)*16;

    for (int ch = 0; ch < 4; ch++) {
        if (ch + 1 < 4) {
            g1_load(sbase, (ch + 1) & 1, ch + 1, m0, c0);
            CP_COMMIT();
            CP_WAIT(1);
        } else {
            CP_WAIT(0);
        }
        __syncthreads();
        uint32_t sb = sbase + (ch & 1)*G1_STAGE;
        uint32_t aRow = sb + aRow0;
#pragma unroll
        for (int s = 0; s < 3; s++) {
            const int sa  = (s == 2) ? 18432 : 0;
            const int sbl = (s == 1) ? 9216  : 0;
#pragma unroll
            for (int kt = 0; kt < 4; kt++) {
                uint32_t a0, a1, a2, a3;
                ldsm_x4(a0, a1, a2, a3, aRow + sa + kt*32);
#pragma unroll
                for (int jj = 0; jj < 4; jj++) {
                    uint32_t ba = sb + 36864 + sbl +
                                  (jj*16 + trow)*144 + kt*32 + kh;
                    uint32_t b0, b1, b2, b3;
                    ldsm_x4(b0, b1, b2, b3, ba);
                    mma_bf16(acc[2*jj],   a0, a1, a2, a3, b0, b1);
                    mma_bf16(acc[2*jj+1], a0, a1, a2, a3, b2, b3);
                }
            }
        }
        __syncthreads();
    }
    const int r0 = m0 + wid*16 + (lane >> 2);
    const int cb = (lane & 3)*2;
#pragma unroll
    for (int j = 0; j < 8; j++) {
        int c = c0 + j*8 + cb;
        float2 bz = *(const float2*)&g_bias1[c];
#pragma unroll
        for (int hrow = 0; hrow < 2; hrow++) {
            int m = r0 + hrow*8;
            *(float2*)&g_hio[(size_t)m*512 + c] =
                make_float2(acc[j][hrow*2] + bz.x, acc[j][hrow*2+1] + bz.y);
        }
    }
}

// ---------------- GEMM2: inp = A @ hio + bias -> bf16 hi/lo -------------------
__global__ void __launch_bounds__(256) gemm2(const float* __restrict__ A,
                                             const float* __restrict__ b_iah,
                                             const float* __restrict__ b_oah) {
    int b = blockIdx.x;
    int q = blockIdx.y; int half = q >> 2; int cq = q & 3;
    __shared__ float As[64][64];
    __shared__ float Hs[64][64];
    int t = threadIdx.x;
#pragma unroll
    for (int f = 0; f < 4; f++) {
        int idx = f*256 + t; int r = idx >> 4; int kq = idx & 15;
        float4 v = *(const float4*)&A[(size_t)b*8192 + r*128 + half*64 + kq*4];
        As[kq*4+0][r] = v.x; As[kq*4+1][r] = v.y;
        As[kq*4+2][r] = v.z; As[kq*4+3][r] = v.w;
        float4 w = *(const float4*)&g_hio[((size_t)b*64 + r)*512 +
                                          half*256 + cq*64 + kq*4];
        *(float4*)&Hs[r][kq*4] = w;
    }
    __syncthreads();
    int ty = t >> 4, tx = t & 15;
    float acc[4][4];
#pragma unroll
    for (int i = 0; i < 4; i++)
#pragma unroll
        for (int j = 0; j < 4; j++) acc[i][j] = 0.f;
#pragma unroll 8
    for (int k = 0; k < 64; k++) {
        float a[4], bv[4];
        *(float4*)a  = *(const float4*)&As[k][ty*4];
        *(float4*)bv = *(const float4*)&Hs[k][tx*4];
#pragma unroll
        for (int i = 0; i < 4; i++)
#pragma unroll
            for (int j = 0; j < 4; j++) acc[i][j] += a[i]*bv[j];
    }
#pragma unroll
    for (int i = 0; i < 4; i++) {
        int n = ty*4 + i;
#pragma unroll
        for (int j = 0; j < 4; j++) {
            int col = cq*64 + tx*4 + j;
            float bias = half ? b_oah[col] : b_iah[col];
            float v = acc[i][j] + bias;
            size_t o = ((size_t)b*64 + n)*512 + half*256 + col;
            __nv_bfloat16 hi, lo; bf_split(v, hi, lo);
            g_inpH[o] = hi; g_inpL[o] = lo;
        }
    }
}

// ---------------- GEMM3: HMMA (mma.sync bf16x3) gates + fused GRU -------------
#define G3_STAGE 92160
#define G3_BIAS  (2*G3_STAGE)                 // 184320
#define G3_SMEM  (G3_BIAS + 1536)

__device__ __forceinline__ void g3_load(uint32_t sbase, int st, int ch,
                                        int m0, int c0) {
    const int t = threadIdx.x;
    uint32_t sb = sbase + st*G3_STAGE;
    const __nv_bfloat16 *Ah, *Al, *Bh, *Bl; int ak, koff;
    if (ch < 8) { Ah=g_inpH; Al=g_inpL; Bh=g_wihH; Bl=g_wihL; ak=512; koff=ch*64; }
    else        { Ah=g_hH;   Al=g_hL;   Bh=g_whhH; Bl=g_whhL; ak=256; koff=(ch-8)*64; }
#pragma unroll
    for (int f = 0; f < 4; f++) {
        int u = f*256 + t; int row = u >> 3, seg = u & 7;
        size_t so = (size_t)(m0+row)*ak + koff + seg*8;
        uint32_t d = sb + row*144 + seg*16;
        cp16(d,         Ah + so);
        cp16(d + 18432, Al + so);
    }
#pragma unroll
    for (int f = 0; f < 6; f++) {
        int u = f*256 + t; int row = u >> 3, seg = u & 7;
        int g = row >> 6, n = row & 63;
        size_t so = (size_t)(g*256 + c0 + n)*ak + koff + seg*8;
        uint32_t d = sb + 36864 + row*144 + seg*16;
        cp16(d,         Bh + so);
        cp16(d + 27648, Bl + so);
    }
}

template<bool GH>
__device__ __forceinline__ void g3_mma_chunk(uint32_t sb, int wid, int lane,
                                             float (&acc)[4][8][4]) {
    uint32_t aRow = sb + (wid*16 + (lane & 15))*144 + (lane >> 4)*16;
    const int midx = lane >> 3;
    const int trow = (midx >> 1)*8 + (lane & 7);
    const int kh   = (midx & 1)*16;
#pragma unroll
    for (int s = 0; s < 3; s++) {
        const int sa = (s == 2) ? 1 : 0;
        const int sbl = (s == 1) ? 1 : 0;
#pragma unroll
        for (int kt = 0; kt < 4; kt++) {
            uint32_t a0, a1, a2, a3;
            ldsm_x4(a0, a1, a2, a3, aRow + sa*18432 + kt*32);
#pragma unroll
            for (int g = 0; g < 3; g++) {
                const int p = (!GH || g < 2) ? g : 3;
#pragma unroll
                for (int jj = 0; jj < 4; jj++) {
                    uint32_t ba = sb + 36864 + sbl*27648 +
                                  (g*64 + jj*16 + trow)*144 + kt*32 + kh;
                    uint32_t b0, b1, b2, b3;
                    ldsm_x4(b0, b1, b2, b3, ba);
                    mma_bf16(acc[p][2*jj],   a0, a1, a2, a3, b0, b1);
                    mma_bf16(acc[p][2*jj+1], a0, a1, a2, a3, b2, b3);
                }
            }
        }
    }
}

__global__ void __launch_bounds__(256) gemm3_mma(const float* __restrict__ b_ih,
                                                 const float* __restrict__ b_hh) {
    extern __shared__ __align__(16) char smem[];
    const int t = threadIdx.x, wid = t >> 5, lane = t & 31;
    const int c0 = blockIdx.x * 64, m0 = blockIdx.y * 128;
    uint32_t sbase = smem_u32(smem);
    float* sbih = (float*)(smem + G3_BIAS);
    float* sbhh = (float*)(smem + G3_BIAS + 768);
    if (t < 64) {
#pragma unroll
        for (int g = 0; g < 3; g++) {
            sbih[g*64 + t] = b_ih[g*256 + c0 + t];
            sbhh[g*64 + t] = b_hh[g*256 + c0 + t];
        }
    }
    float acc[4][8][4];
#pragma unroll
    for (int p = 0; p < 4; p++)
#pragma unroll
        for (int j = 0; j < 8; j++)
#pragma unroll
            for (int i = 0; i < 4; i++) acc[p][j][i] = 0.f;

    g3_load(sbase, 0, 0, m0, c0);
    CP_COMMIT();

    for (int ch = 0; ch < 12; ch++) {
        if (ch + 1 < 12) {
            g3_load(sbase, (ch + 1) & 1, ch + 1, m0, c0);
            CP_COMMIT();
            CP_WAIT(1);
        } else {
            CP_WAIT(0);
        }
        __syncthreads();
        uint32_t sb = sbase + (ch & 1)*G3_STAGE;
        if (ch < 8) g3_mma_chunk<false>(sb, wid, lane, acc);
        else        g3_mma_chunk<true >(sb, wid, lane, acc);
        __syncthreads();
    }

    const int r0 = m0 + wid*16 + (lane >> 2);
    const int cb = (lane & 3)*2;
#pragma unroll
    for (int j = 0; j < 8; j++) {
        int c = c0 + j*8 + cb;
#pragma unroll
        for (int hrow = 0; hrow < 2; hrow++) {
            int m = r0 + hrow*8;
            float2 ho = *(const float2*)&g_h[(size_t)m*256 + c];
            float o[2];
#pragma unroll
            for (int e = 0; e < 2; e++) {
                int cl = j*8 + cb + e;
                int fi = hrow*2 + e;
                float r = 1.f/(1.f + expf(-(acc[0][j][fi] + sbih[cl] + sbhh[cl])));
                float z = 1.f/(1.f + expf(-(acc[1][j][fi] + sbih[64+cl] + sbhh[64+cl])));
                float nn = tanhf(acc[2][j][fi] + sbih[128+cl] +
                                 r*(acc[3][j][fi] + sbhh[128+cl]));
                float hv = e ? ho.y : ho.x;
                o[e] = nn + z*(hv - nn);
            }
            *(float2*)&g_hn[(size_t)m*256 + c] = make_float2(o[0], o[1]);
        }
    }
}

// ---------------- attention / star update ------------------------------------
__global__ void __launch_bounds__(256) attn(const float* __restrict__ mask,
                                            float* __restrict__ out,
                                            int final_) {
    int b = blockIdx.x, t = threadIdx.x, lane = t & 31, w = t >> 5;
    __shared__ float s_star[256];
    __shared__ float s_alpha[64];
    __shared__ float s_v[64];
    __shared__ float s_p[64];
    s_star[t] = g_star[(size_t)b*256 + t];
    __syncthreads();
#pragma unroll
    for (int r = 0; r < 8; r++) {
        int n = w*8 + r;
        const float* hr = &g_hn[((size_t)b*64 + n)*256];
        float p = 0.f;
#pragma unroll
        for (int j = lane; j < 256; j += 32) p += hr[j] * s_star[j];
#pragma unroll
        for (int o = 16; o; o >>= 1) p += __shfl_xor_sync(0xffffffffu, p, o);
        if (lane == 0) s_v[n] = p;
    }
    __syncthreads();
    float ss = 0.f;
#pragma unroll 8
    for (int j = 0; j < 256; j++) { float x = s_star[j]; ss += x*x; }
    if (t < 64) {
        float sraw = s_v[t];
        float a = 1.f / (1.f + expf(-sraw * 0.0625f));
        s_alpha[t] = a;
        float d2 = (1.f - a)*sraw + a*ss;
        s_v[t] = expf(d2) * mask[(size_t)b*64 + t];
    }
    __syncthreads();
    float den = 1e-24f;
#pragma unroll
    for (int n = 0; n < 64; n++) den += s_v[n];
    if (t < 64) s_p[t] = s_v[t] / den;
    __syncthreads();
    float st = s_star[t];
    float accS = 0.f;
#pragma unroll 4
    for (int n = 0; n < 64; n++) {
        float a = s_alpha[n];
        size_t idx = ((size_t)b*64 + n)*256 + t;
        float h2 = (1.f - a)*g_hn[idx] + a*st;
        g_h[idx] = h2;
        __nv_bfloat16 hi, lo; bf_split(h2, hi, lo);
        g_hH[idx] = hi; g_hL[idx] = lo;
        if (final_) out[idx] = h2;
        accS += s_p[n] * h2;
    }
    g_star[(size_t)b*256 + t] = accS;
    if (final_) out[(size_t)Bb*Nn*Hh + (size_t)b*256 + t] = accS;
}

// ---------------- launch ------------------------------------------------------
extern "C" void kernel_launch(void* const* d_in, const int* in_sizes, int n_in,
                              void* d_out, int out_size) {
    const float* A      = (const float*)d_in[0];
    const float* hidden = (const float*)d_in[1];
    const float* mask   = (const float*)d_in[2];
    const float* w_ih   = (const float*)d_in[3];
    const float* w_hh   = (const float*)d_in[4];
    const float* b_ih   = (const float*)d_in[5];
    const float* b_hh   = (const float*)d_in[6];
    const float* b_iah  = (const float*)d_in[7];
    const float* b_oah  = (const float*)d_in[8];
    const float* W_in   = (const float*)d_in[9];
    const float* b_in   = (const float*)d_in[10];
    const float* W_out  = (const float*)d_in[11];
    const float* b_out  = (const float*)d_in[12];
    float* out = (float*)d_out;

    cudaFuncSetAttribute(gemm1_mma, cudaFuncAttributeMaxDynamicSharedMemorySize,
                         G1_SMEM);
    cudaFuncSetAttribute(gemm3_mma, cudaFuncAttributeMaxDynamicSharedMemorySize,
                         G3_SMEM);

    setup_weights<<<1536, 256>>>(W_in, b_in, W_out, b_out, w_ih, w_hh);
    copy_h<<<4096, 256>>>(hidden);
    star_init<<<Bb, 256>>>(hidden, mask);

    for (int s = 0; s < 2; s++) {
        gemm1_mma<<<dim3(8, MTOT/128), 256, G1_SMEM>>>();
        gemm2<<<dim3(Bb, 8), 256>>>(A, b_iah, b_oah);
        gemm3_mma<<<dim3(4, MTOT/128), 256, G3_SMEM>>>(b_ih, b_hh);
        attn<<<Bb, 256>>>(mask, out, s == 1);
    }
}

// round 6
// speedup vs baseline: 3.3250x; 1.7434x over previous
#include <cuda_runtime.h>
#include <cuda_fp16.h>
#include <math.h>
#include <cstdint>

#define Bb   2048
#define Nn   64
#define Hh   256
#define MTOT (Bb*Nn)          // 131072

// ---------------- scratch (static device globals; no allocations) ----------
__device__ float g_h   [MTOT*Hh];         // current hidden (fp32)
__device__ float g_hn  [MTOT*Hh];         // hidden after GRU cell
__device__ float g_star[Bb*Hh];
__device__ float g_bias1[512];
// fp16 split activations / rounded weights
__device__ __half g_hH  [MTOT*256];
__device__ __half g_hL  [MTOT*256];
__device__ __half g_hioH[MTOT*512];
__device__ __half g_hioL[MTOT*512];
__device__ __half g_inpH[MTOT*512];
__device__ __half g_inpL[MTOT*512];
__device__ __half g_AH  [Bb*64*128];
__device__ __half g_AL  [Bb*64*128];
__device__ __half g_w1  [512*256];        // [c][k]: c<256 W_in, else W_out
__device__ __half g_wih [768*512];        // [n][k]
__device__ __half g_whh [768*256];

// ---------------- helpers ----------------------------------------------------
__device__ __forceinline__ uint32_t smem_u32(const void* p) {
    uint32_t a;
    asm("{ .reg .u64 t; cvta.to.shared.u64 t, %1; cvt.u32.u64 %0, t; }"
        : "=r"(a) : "l"(p));
    return a;
}
__device__ __forceinline__ void cp16(uint32_t dst, const void* src) {
    asm volatile("cp.async.cg.shared.global [%0], [%1], 16;"
                 :: "r"(dst), "l"(src) : "memory");
}
#define CP_COMMIT() asm volatile("cp.async.commit_group;" ::: "memory")
#define CP_WAIT(n)  asm volatile("cp.async.wait_group %0;" :: "n"(n) : "memory")

__device__ __forceinline__ void ldsm_x4(uint32_t& r0, uint32_t& r1,
                                        uint32_t& r2, uint32_t& r3,
                                        uint32_t addr) {
    asm volatile("ldmatrix.sync.aligned.m8n8.x4.shared.b16 {%0,%1,%2,%3}, [%4];"
                 : "=r"(r0), "=r"(r1), "=r"(r2), "=r"(r3) : "r"(addr));
}
__device__ __forceinline__ void ldsm_x4_t(uint32_t& r0, uint32_t& r1,
                                          uint32_t& r2, uint32_t& r3,
                                          uint32_t addr) {
    asm volatile("ldmatrix.sync.aligned.m8n8.x4.trans.shared.b16 {%0,%1,%2,%3}, [%4];"
                 : "=r"(r0), "=r"(r1), "=r"(r2), "=r"(r3) : "r"(addr));
}
__device__ __forceinline__ void mma_f16(float* d,
                                        uint32_t a0, uint32_t a1,
                                        uint32_t a2, uint32_t a3,
                                        uint32_t b0, uint32_t b1) {
    asm volatile(
        "mma.sync.aligned.m16n8k16.row.col.f32.f16.f16.f32 "
        "{%0,%1,%2,%3}, {%4,%5,%6,%7}, {%8,%9}, {%0,%1,%2,%3};"
        : "+f"(d[0]), "+f"(d[1]), "+f"(d[2]), "+f"(d[3])
        : "r"(a0), "r"(a1), "r"(a2), "r"(a3), "r"(b0), "r"(b1));
}
__device__ __forceinline__ void h_split(float v, __half& hi, __half& lo) {
    hi = __float2half_rn(v);
    lo = __float2half_rn(v - __half2float(hi));
}

// ---------------- setup -------------------------------------------------------
__global__ void setup_weights(const float* __restrict__ W_in,
                              const float* __restrict__ b_in,
                              const float* __restrict__ W_out,
                              const float* __restrict__ b_out,
                              const float* __restrict__ w_ih,
                              const float* __restrict__ w_hh) {
    int i = blockIdx.x * blockDim.x + threadIdx.x;
    if (i < 512) g_bias1[i] = (i < 256) ? b_in[i] : b_out[i-256];
    if (i < 512*256) {
        int c = i >> 8, k = i & 255;
        float v = (c < 256) ? W_in[c*256 + k] : W_out[(c-256)*256 + k];
        g_w1[i] = __float2half_rn(v);
    }
    if (i < 768*512) g_wih[i] = __float2half_rn(w_ih[i]);
    if (i < 768*256) g_whh[i] = __float2half_rn(w_hh[i]);
}

__global__ void setup_A(const float* __restrict__ A) {
    size_t n = (size_t)Bb*64*128;
    for (size_t i = blockIdx.x*(size_t)blockDim.x + threadIdx.x; i < n;
         i += (size_t)gridDim.x*blockDim.x) {
        __half hi, lo; h_split(A[i], hi, lo);
        g_AH[i] = hi; g_AL[i] = lo;
    }
}

__global__ void copy_h(const float* __restrict__ src) {
    size_t n = (size_t)MTOT*256;
    for (size_t i = blockIdx.x*(size_t)blockDim.x + threadIdx.x; i < n;
         i += (size_t)gridDim.x*blockDim.x) {
        float v = src[i];
        g_h[i] = v;
        __half hi, lo; h_split(v, hi, lo);
        g_hH[i] = hi; g_hL[i] = lo;
    }
}

__global__ void star_init(const float* __restrict__ hidden,
                          const float* __restrict__ mask) {
    int b = blockIdx.x, t = threadIdx.x;
    float len = 0.f;
#pragma unroll 8
    for (int n = 0; n < 64; n++) len += mask[b*64 + n];
    float acc = 0.f;
    for (int n = 0; n < 64; n++)
        acc += hidden[((size_t)b*64 + n)*256 + t] * mask[b*64 + n];
    g_star[(size_t)b*256 + t] = acc / len;
}

// ---------------- GEMM1 (fp16x2): hio = h @ [W_in^T|W_out^T] + bias ----------
#define G1_STAGE 46080   // A hi 18432 + A lo 18432 + B 9216
#define G1_SMEM  (2*G1_STAGE)

__device__ __forceinline__ void g1_load(uint32_t sbase, int st, int ch,
                                        int m0, int c0) {
    const int t = threadIdx.x;
    uint32_t sb = sbase + st*G1_STAGE;
    int koff = ch*64;
#pragma unroll
    for (int f = 0; f < 4; f++) {
        int u = f*256 + t; int row = u >> 3, seg = u & 7;
        size_t so = (size_t)(m0+row)*256 + koff + seg*8;
        uint32_t d = sb + row*144 + seg*16;
        cp16(d,         g_hH + so);
        cp16(d + 18432, g_hL + so);
    }
#pragma unroll
    for (int f = 0; f < 2; f++) {
        int u = f*256 + t; int row = u >> 3, seg = u & 7;
        cp16(sb + 36864 + row*144 + seg*16,
             g_w1 + (size_t)(c0+row)*256 + koff + seg*8);
    }
}

__global__ void __launch_bounds__(256, 2) gemm1_mma() {
    extern __shared__ __align__(16) char smem[];
    const int t = threadIdx.x, wid = t >> 5, lane = t & 31;
    const int c0 = blockIdx.x * 64, m0 = blockIdx.y * 128;
    uint32_t sbase = smem_u32(smem);
    float acc[8][4];
#pragma unroll
    for (int j = 0; j < 8; j++)
#pragma unroll
        for (int i = 0; i < 4; i++) acc[j][i] = 0.f;

    g1_load(sbase, 0, 0, m0, c0);
    CP_COMMIT();

    const uint32_t aRow0 = (wid*16 + (lane & 15))*144 + (lane >> 4)*16;
    const int midx = lane >> 3;
    const int trow = (midx >> 1)*8 + (lane & 7);
    const int kh   = (midx & 1)*16;

    for (int ch = 0; ch < 4; ch++) {
        if (ch + 1 < 4) {
            g1_load(sbase, (ch + 1) & 1, ch + 1, m0, c0);
            CP_COMMIT();
            CP_WAIT(1);
        } else {
            CP_WAIT(0);
        }
        __syncthreads();
        uint32_t sb = sbase + (ch & 1)*G1_STAGE;
        uint32_t aRow = sb + aRow0;
#pragma unroll
        for (int kt = 0; kt < 4; kt++) {
            uint32_t ah0, ah1, ah2, ah3, al0, al1, al2, al3;
            ldsm_x4(ah0, ah1, ah2, ah3, aRow + kt*32);
            ldsm_x4(al0, al1, al2, al3, aRow + 18432 + kt*32);
#pragma unroll
            for (int jj = 0; jj < 4; jj++) {
                uint32_t ba = sb + 36864 + (jj*16 + trow)*144 + kt*32 + kh;
                uint32_t b0, b1, b2, b3;
                ldsm_x4(b0, b1, b2, b3, ba);
                mma_f16(acc[2*jj],   ah0, ah1, ah2, ah3, b0, b1);
                mma_f16(acc[2*jj+1], ah0, ah1, ah2, ah3, b2, b3);
                mma_f16(acc[2*jj],   al0, al1, al2, al3, b0, b1);
                mma_f16(acc[2*jj+1], al0, al1, al2, al3, b2, b3);
            }
        }
        __syncthreads();
    }
    const int r0 = m0 + wid*16 + (lane >> 2);
    const int cb = (lane & 3)*2;
#pragma unroll
    for (int j = 0; j < 8; j++) {
        int c = c0 + j*8 + cb;
        float2 bz = *(const float2*)&g_bias1[c];
#pragma unroll
        for (int hrow = 0; hrow < 2; hrow++) {
            int m = r0 + hrow*8;
            float v0 = acc[j][hrow*2]   + bz.x;
            float v1 = acc[j][hrow*2+1] + bz.y;
            __half h0, l0, h1, l1;
            h_split(v0, h0, l0); h_split(v1, h1, l1);
            *(__half2*)&g_hioH[(size_t)m*512 + c] = __halves2half2(h0, h1);
            *(__half2*)&g_hioL[(size_t)m*512 + c] = __halves2half2(l0, l1);
        }
    }
}

// ---------------- GEMM2 (fp16x3): inp = A_adj @ hio + bias --------------------
// CTA per (b, half): M=64 nodes, N=256 cols, K=64. A split + hio split.
#define G2_A   0          // 2 planes x 64 x 144 = 18432
#define G2_B   18432      // 2 planes x 64 x 528 = 67584
#define G2_SMEM 86016

__global__ void __launch_bounds__(256, 2) gemm2_mma(const float* __restrict__ b_iah,
                                                    const float* __restrict__ b_oah) {
    extern __shared__ __align__(16) char smem[];
    const int t = threadIdx.x, wid = t >> 5, lane = t & 31;
    const int b = blockIdx.x, half_ = blockIdx.y;
    uint32_t sbase = smem_u32(smem);
    // load A: 2 planes x 64 rows x 8 segs (128B row of K=64 halves)
#pragma unroll
    for (int f = 0; f < 4; f++) {
        int u = f*256 + t; int pl = u >> 9, row = (u >> 3) & 63, seg = u & 7;
        const __half* src = pl ? g_AL : g_AH;
        cp16(sbase + G2_A + pl*9216 + row*144 + seg*16,
             src + (size_t)b*8192 + row*128 + half_*64 + seg*8);
    }
    // load hio tile: 2 planes x 64 rows x 32 segs (512B row of 256 halves)
#pragma unroll
    for (int f = 0; f < 16; f++) {
        int u = f*256 + t; int pl = u >> 11, row = (u >> 5) & 63, seg = u & 31;
        const __half* src = pl ? g_hioL : g_hioH;
        cp16(sbase + G2_B + pl*33792 + row*528 + seg*16,
             src + ((size_t)b*64 + row)*512 + half_*256 + seg*8);
    }
    CP_COMMIT(); CP_WAIT(0);
    __syncthreads();

    const int wr = wid >> 2, wc = wid & 3;
    float acc[2][8][4];
#pragma unroll
    for (int r = 0; r < 2; r++)
#pragma unroll
        for (int j = 0; j < 8; j++)
#pragma unroll
            for (int i = 0; i < 4; i++) acc[r][j][i] = 0.f;

    uint32_t aBase = sbase + G2_A + (wr*32 + (lane & 15))*144 + (lane >> 4)*16;
#pragma unroll
    for (int kt = 0; kt < 4; kt++) {
        uint32_t ah[2][4], al[2][4];
#pragma unroll
        for (int r = 0; r < 2; r++) {
            ldsm_x4(ah[r][0], ah[r][1], ah[r][2], ah[r][3],
                    aBase + r*2304 + kt*32);
            ldsm_x4(al[r][0], al[r][1], al[r][2], al[r][3],
                    aBase + 9216 + r*2304 + kt*32);
        }
#pragma unroll
        for (int jj = 0; jj < 4; jj++) {
            uint32_t ba = sbase + G2_B + (kt*16 + (lane & 15))*528 +
                          (wc*64 + jj*16 + (lane >> 4)*8)*2;
            uint32_t bh0, bh1, bh2, bh3, bl0, bl1, bl2, bl3;
            ldsm_x4_t(bh0, bh1, bh2, bh3, ba);
            ldsm_x4_t(bl0, bl1, bl2, bl3, ba + 33792);
#pragma unroll
            for (int r = 0; r < 2; r++) {
                mma_f16(acc[r][jj*2],   ah[r][0], ah[r][1], ah[r][2], ah[r][3], bh0, bh1);
                mma_f16(acc[r][jj*2+1], ah[r][0], ah[r][1], ah[r][2], ah[r][3], bh2, bh3);
                mma_f16(acc[r][jj*2],   al[r][0], al[r][1], al[r][2], al[r][3], bh0, bh1);
                mma_f16(acc[r][jj*2+1], al[r][0], al[r][1], al[r][2], al[r][3], bh2, bh3);
                mma_f16(acc[r][jj*2],   ah[r][0], ah[r][1], ah[r][2], ah[r][3], bl0, bl1);
                mma_f16(acc[r][jj*2+1], ah[r][0], ah[r][1], ah[r][2], ah[r][3], bl2, bl3);
            }
        }
    }
    const float* bias = half_ ? b_oah : b_iah;
#pragma unroll
    for (int r = 0; r < 2; r++) {
        int n = wr*32 + r*16 + (lane >> 2);
#pragma unroll
        for (int j = 0; j < 8; j++) {
            int col = wc*64 + j*8 + (lane & 3)*2;
#pragma unroll
            for (int hrow = 0; hrow < 2; hrow++) {
                int nn = n + hrow*8;
                float v0 = acc[r][j][hrow*2]   + bias[col];
                float v1 = acc[r][j][hrow*2+1] + bias[col+1];
                __half h0, l0, h1, l1;
                h_split(v0, h0, l0); h_split(v1, h1, l1);
                size_t o = ((size_t)b*64 + nn)*512 + half_*256 + col;
                *(__half2*)&g_inpH[o] = __halves2half2(h0, h1);
                *(__half2*)&g_inpL[o] = __halves2half2(l0, l1);
            }
        }
    }
}

// ---------------- GEMM3 (fp16x2): gates + fused GRU ---------------------------
// CTA 128 rows x 32 cols x 4 planes. Warps 4 row-groups x 2 col-groups.
#define G3_B     36864    // A hi 18432 + A lo 18432
#define G3_STAGE 50688    // + B 96 x 144 = 13824
#define G3_BIAS  (2*G3_STAGE)
#define G3_SMEM  (G3_BIAS + 768)

__device__ __forceinline__ void g3_load(uint32_t sbase, int st, int ch,
                                        int m0, int c0) {
    const int t = threadIdx.x;
    uint32_t sb = sbase + st*G3_STAGE;
    const __half *Ah, *Al, *Bw; int ak, koff;
    if (ch < 8) { Ah = g_inpH; Al = g_inpL; Bw = g_wih; ak = 512; koff = ch*64; }
    else        { Ah = g_hH;   Al = g_hL;   Bw = g_whh; ak = 256; koff = (ch-8)*64; }
#pragma unroll
    for (int f = 0; f < 4; f++) {
        int u = f*256 + t; int row = u >> 3, seg = u & 7;
        size_t so = (size_t)(m0+row)*ak + koff + seg*8;
        uint32_t d = sb + row*144 + seg*16;
        cp16(d,         Ah + so);
        cp16(d + 18432, Al + so);
    }
#pragma unroll
    for (int f = 0; f < 3; f++) {
        int u = f*256 + t; int row = u >> 3, seg = u & 7;
        int g = row >> 5, n = row & 31;
        cp16(sb + G3_B + row*144 + seg*16,
             Bw + (size_t)(g*256 + c0 + n)*ak + koff + seg*8);
    }
}

template<bool GH>
__device__ __forceinline__ void g3_mma_chunk(uint32_t sb, int wr, int wc, int lane,
                                             float (&acc)[4][2][2][4]) {
    uint32_t aBase = sb + (wr*32 + (lane & 15))*144 + (lane >> 4)*16;
    const int midx = lane >> 3;
    const int trow = (midx >> 1)*8 + (lane & 7);
    const int kh   = (midx & 1)*16;
#pragma unroll
    for (int kt = 0; kt < 4; kt++) {
        uint32_t a[2][2][4];
#pragma unroll
        for (int r = 0; r < 2; r++) {
            ldsm_x4(a[r][0][0], a[r][0][1], a[r][0][2], a[r][0][3],
                    aBase + r*2304 + kt*32);
            ldsm_x4(a[r][1][0], a[r][1][1], a[r][1][2], a[r][1][3],
                    aBase + 18432 + r*2304 + kt*32);
        }
#pragma unroll
        for (int g = 0; g < 3; g++) {
            const int p = (!GH || g < 2) ? g : 3;
            uint32_t b0, b1, b2, b3;
            ldsm_x4(b0, b1, b2, b3,
                    sb + G3_B + (g*32 + wc*16 + trow)*144 + kt*32 + kh);
#pragma unroll
            for (int r = 0; r < 2; r++) {
#pragma unroll
                for (int s = 0; s < 2; s++) {
                    mma_f16(acc[p][r][0], a[r][s][0], a[r][s][1],
                            a[r][s][2], a[r][s][3], b0, b1);
                    mma_f16(acc[p][r][1], a[r][s][0], a[r][s][1],
                            a[r][s][2], a[r][s][3], b2, b3);
                }
            }
        }
    }
}

__global__ void __launch_bounds__(256, 2) gemm3_mma(const float* __restrict__ b_ih,
                                                    const float* __restrict__ b_hh) {
    extern __shared__ __align__(16) char smem[];
    const int t = threadIdx.x, wid = t >> 5, lane = t & 31;
    const int c0 = blockIdx.x * 32, m0 = blockIdx.y * 128;
    const int wr = wid & 3, wc = wid >> 2;
    uint32_t sbase = smem_u32(smem);
    float* sbih = (float*)(smem + G3_BIAS);
    float* sbhh = (float*)(smem + G3_BIAS + 384);
    if (t < 32) {
#pragma unroll
        for (int g = 0; g < 3; g++) {
            sbih[g*32 + t] = b_ih[g*256 + c0 + t];
            sbhh[g*32 + t] = b_hh[g*256 + c0 + t];
        }
    }
    float acc[4][2][2][4];
#pragma unroll
    for (int p = 0; p < 4; p++)
#pragma unroll
        for (int r = 0; r < 2; r++)
#pragma unroll
            for (int cgi = 0; cgi < 2; cgi++)
#pragma unroll
                for (int i = 0; i < 4; i++) acc[p][r][cgi][i] = 0.f;

    g3_load(sbase, 0, 0, m0, c0);
    CP_COMMIT();

    for (int ch = 0; ch < 12; ch++) {
        if (ch + 1 < 12) {
            g3_load(sbase, (ch + 1) & 1, ch + 1, m0, c0);
            CP_COMMIT();
            CP_WAIT(1);
        } else {
            CP_WAIT(0);
        }
        __syncthreads();
        uint32_t sb = sbase + (ch & 1)*G3_STAGE;
        if (ch < 8) g3_mma_chunk<false>(sb, wr, wc, lane, acc);
        else        g3_mma_chunk<true >(sb, wr, wc, lane, acc);
        __syncthreads();
    }

    // GRU epilogue
    const int rbase = m0 + wr*32 + (lane >> 2);
    const int cb = (lane & 3)*2;
#pragma unroll
    for (int r = 0; r < 2; r++) {
#pragma unroll
        for (int cgi = 0; cgi < 2; cgi++) {
            int cl = wc*16 + cgi*8 + cb;       // local col 0..31
            int c  = c0 + cl;
#pragma unroll
            for (int hrow = 0; hrow < 2; hrow++) {
                int m = rbase + r*16 + hrow*8;
                float2 ho = *(const float2*)&g_h[(size_t)m*256 + c];
                float o[2];
#pragma unroll
                for (int e = 0; e < 2; e++) {
                    int li = cl + e;
                    int fi = hrow*2 + e;
                    float rr = 1.f/(1.f + expf(-(acc[0][r][cgi][fi] +
                                                 sbih[li] + sbhh[li])));
                    float zz = 1.f/(1.f + expf(-(acc[1][r][cgi][fi] +
                                                 sbih[32+li] + sbhh[32+li])));
                    float nn = tanhf(acc[2][r][cgi][fi] + sbih[64+li] +
                                     rr*(acc[3][r][cgi][fi] + sbhh[64+li]));
                    float hv = e ? ho.y : ho.x;
                    o[e] = nn + zz*(hv - nn);
                }
                *(float2*)&g_hn[(size_t)m*256 + c] = make_float2(o[0], o[1]);
            }
        }
    }
}

// ---------------- attention / star update ------------------------------------
__global__ void __launch_bounds__(256) attn(const float* __restrict__ mask,
                                            float* __restrict__ out,
                                            int final_) {
    int b = blockIdx.x, t = threadIdx.x, lane = t & 31, w = t >> 5;
    __shared__ float s_star[256];
    __shared__ float s_alpha[64];
    __shared__ float s_v[64];
    __shared__ float s_p[64];
    s_star[t] = g_star[(size_t)b*256 + t];
    __syncthreads();
#pragma unroll
    for (int r = 0; r < 8; r++) {
        int n = w*8 + r;
        const float* hr = &g_hn[((size_t)b*64 + n)*256];
        float p = 0.f;
#pragma unroll
        for (int j = lane; j < 256; j += 32) p += hr[j] * s_star[j];
#pragma unroll
        for (int o = 16; o; o >>= 1) p += __shfl_xor_sync(0xffffffffu, p, o);
        if (lane == 0) s_v[n] = p;
    }
    __syncthreads();
    float ss = 0.f;
#pragma unroll 8
    for (int j = 0; j < 256; j++) { float x = s_star[j]; ss += x*x; }
    if (t < 64) {
        float sraw = s_v[t];
        float a = 1.f / (1.f + expf(-sraw * 0.0625f));
        s_alpha[t] = a;
        float d2 = (1.f - a)*sraw + a*ss;
        s_v[t] = expf(d2) * mask[(size_t)b*64 + t];
    }
    __syncthreads();
    float den = 1e-24f;
#pragma unroll
    for (int n = 0; n < 64; n++) den += s_v[n];
    if (t < 64) s_p[t] = s_v[t] / den;
    __syncthreads();
    float st = s_star[t];
    float accS = 0.f;
#pragma unroll 4
    for (int n = 0; n < 64; n++) {
        float a = s_alpha[n];
        size_t idx = ((size_t)b*64 + n)*256 + t;
        float h2 = (1.f - a)*g_hn[idx] + a*st;
        g_h[idx] = h2;
        __half hi, lo; h_split(h2, hi, lo);
        g_hH[idx] = hi; g_hL[idx] = lo;
        if (final_) out[idx] = h2;
        accS += s_p[n] * h2;
    }
    g_star[(size_t)b*256 + t] = accS;
    if (final_) out[(size_t)Bb*Nn*Hh + (size_t)b*256 + t] = accS;
}

// ---------------- launch ------------------------------------------------------
extern "C" void kernel_launch(void* const* d_in, const int* in_sizes, int n_in,
                              void* d_out, int out_size) {
    const float* A      = (const float*)d_in[0];
    const float* hidden = (const float*)d_in[1];
    const float* mask   = (const float*)d_in[2];
    const float* w_ih   = (const float*)d_in[3];
    const float* w_hh   = (const float*)d_in[4];
    const float* b_ih   = (const float*)d_in[5];
    const float* b_hh   = (const float*)d_in[6];
    const float* b_iah  = (const float*)d_in[7];
    const float* b_oah  = (const float*)d_in[8];
    const float* W_in   = (const float*)d_in[9];
    const float* b_in   = (const float*)d_in[10];
    const float* W_out  = (const float*)d_in[11];
    const float* b_out  = (const float*)d_in[12];
    float* out = (float*)d_out;

    cudaFuncSetAttribute(gemm1_mma, cudaFuncAttributeMaxDynamicSharedMemorySize, G1_SMEM);
    cudaFuncSetAttribute(gemm2_mma, cudaFuncAttributeMaxDynamicSharedMemorySize, G2_SMEM);
    cudaFuncSetAttribute(gemm3_mma, cudaFuncAttributeMaxDynamicSharedMemorySize, G3_SMEM);

    setup_weights<<<1536, 256>>>(W_in, b_in, W_out, b_out, w_ih, w_hh);
    setup_A<<<4096, 256>>>(A);
    copy_h<<<4096, 256>>>(hidden);
    star_init<<<Bb, 256>>>(hidden, mask);

    for (int s = 0; s < 2; s++) {
        gemm1_mma<<<dim3(8, 1024), 256, G1_SMEM>>>();
        gemm2_mma<<<dim3(Bb, 2), 256, G2_SMEM>>>(b_iah, b_oah);
        gemm3_mma<<<dim3(8, 1024), 256, G3_SMEM>>>(b_ih, b_hh);
        attn<<<Bb, 256>>>(mask, out, s == 1);
    }
}

// round 7
// speedup vs baseline: 4.3326x; 1.3030x over previous
#include <cuda_runtime.h>
#include <cuda_fp16.h>
#include <math.h>
#include <cstdint>

#define Bb   2048
#define Nn   64
#define Hh   256
#define MTOT (Bb*Nn)          // 131072

// ---------------- scratch (static device globals; no allocations) ----------
__device__ float g_hn  [MTOT*Hh];         // hidden after GRU cell (fp32)
__device__ float g_star[Bb*Hh];
__device__ float g_bias1[512];
// fp16 split activations / rounded weights
__device__ __half g_hH  [MTOT*256];
__device__ __half g_hL  [MTOT*256];
__device__ __half g_hioH[MTOT*512];
__device__ __half g_hioL[MTOT*512];
__device__ __half g_inpH[MTOT*512];
__device__ __half g_AH  [Bb*64*128];
__device__ __half g_AL  [Bb*64*128];
__device__ __half g_w1  [512*256];        // [c][k]: c<256 W_in, else W_out
__device__ __half g_wih [768*512];        // [n][k]
__device__ __half g_whh [768*256];

// ---------------- helpers ----------------------------------------------------
__device__ __forceinline__ uint32_t smem_u32(const void* p) {
    uint32_t a;
    asm("{ .reg .u64 t; cvta.to.shared.u64 t, %1; cvt.u32.u64 %0, t; }"
        : "=r"(a) : "l"(p));
    return a;
}
__device__ __forceinline__ void cp16(uint32_t dst, const void* src) {
    asm volatile("cp.async.cg.shared.global [%0], [%1], 16;"
                 :: "r"(dst), "l"(src) : "memory");
}
#define CP_COMMIT() asm volatile("cp.async.commit_group;" ::: "memory")
#define CP_WAIT(n)  asm volatile("cp.async.wait_group %0;" :: "n"(n) : "memory")

__device__ __forceinline__ void ldsm_x4(uint32_t& r0, uint32_t& r1,
                                        uint32_t& r2, uint32_t& r3,
                                        uint32_t addr) {
    asm volatile("ldmatrix.sync.aligned.m8n8.x4.shared.b16 {%0,%1,%2,%3}, [%4];"
                 : "=r"(r0), "=r"(r1), "=r"(r2), "=r"(r3) : "r"(addr));
}
__device__ __forceinline__ void ldsm_x4_t(uint32_t& r0, uint32_t& r1,
                                          uint32_t& r2, uint32_t& r3,
                                          uint32_t addr) {
    asm volatile("ldmatrix.sync.aligned.m8n8.x4.trans.shared.b16 {%0,%1,%2,%3}, [%4];"
                 : "=r"(r0), "=r"(r1), "=r"(r2), "=r"(r3) : "r"(addr));
}
__device__ __forceinline__ void mma_f16(float* d,
                                        uint32_t a0, uint32_t a1,
                                        uint32_t a2, uint32_t a3,
                                        uint32_t b0, uint32_t b1) {
    asm volatile(
        "mma.sync.aligned.m16n8k16.row.col.f32.f16.f16.f32 "
        "{%0,%1,%2,%3}, {%4,%5,%6,%7}, {%8,%9}, {%0,%1,%2,%3};"
        : "+f"(d[0]), "+f"(d[1]), "+f"(d[2]), "+f"(d[3])
        : "r"(a0), "r"(a1), "r"(a2), "r"(a3), "r"(b0), "r"(b1));
}
__device__ __forceinline__ void h_split(float v, __half& hi, __half& lo) {
    hi = __float2half_rn(v);
    lo = __float2half_rn(v - __half2float(hi));
}

// ---------------- setup -------------------------------------------------------
__global__ void setup_weights(const float* __restrict__ W_in,
                              const float* __restrict__ b_in,
                              const float* __restrict__ W_out,
                              const float* __restrict__ b_out,
                              const float* __restrict__ w_ih,
                              const float* __restrict__ w_hh) {
    int i = blockIdx.x * blockDim.x + threadIdx.x;
    if (i < 512) g_bias1[i] = (i < 256) ? b_in[i] : b_out[i-256];
    if (i < 512*256) {
        int c = i >> 8, k = i & 255;
        float v = (c < 256) ? W_in[c*256 + k] : W_out[(c-256)*256 + k];
        g_w1[i] = __float2half_rn(v);
    }
    if (i < 768*512) g_wih[i] = __float2half_rn(w_ih[i]);
    if (i < 768*256) g_whh[i] = __float2half_rn(w_hh[i]);
}

__global__ void setup_A(const float* __restrict__ A) {
    size_t n = (size_t)Bb*64*128;
    for (size_t i = blockIdx.x*(size_t)blockDim.x + threadIdx.x; i < n;
         i += (size_t)gridDim.x*blockDim.x) {
        __half hi, lo; h_split(A[i], hi, lo);
        g_AH[i] = hi; g_AL[i] = lo;
    }
}

// fused: split hidden into hH/hL + compute star (masked mean)
__global__ void __launch_bounds__(256) init_h(const float* __restrict__ hidden,
                                              const float* __restrict__ mask) {
    int b = blockIdx.x, t = threadIdx.x;
    float len = 0.f, acc = 0.f;
#pragma unroll 4
    for (int n = 0; n < 64; n++) {
        float mk = mask[b*64 + n];
        size_t idx = ((size_t)b*64 + n)*256 + t;
        float v = hidden[idx];
        __half hi, lo; h_split(v, hi, lo);
        g_hH[idx] = hi; g_hL[idx] = lo;
        acc += v * mk; len += mk;
    }
    g_star[(size_t)b*256 + t] = acc / len;
}

// ---------------- GEMM1 (fp16x2): hio = h @ [W_in^T|W_out^T] + bias ----------
#define G1_STAGE 46080   // A hi 18432 + A lo 18432 + B 9216
#define G1_SMEM  (2*G1_STAGE)

__device__ __forceinline__ void g1_load(uint32_t sbase, int st, int ch,
                                        int m0, int c0) {
    const int t = threadIdx.x;
    uint32_t sb = sbase + st*G1_STAGE;
    int koff = ch*64;
#pragma unroll
    for (int f = 0; f < 4; f++) {
        int u = f*256 + t; int row = u >> 3, seg = u & 7;
        size_t so = (size_t)(m0+row)*256 + koff + seg*8;
        uint32_t d = sb + row*144 + seg*16;
        cp16(d,         g_hH + so);
        cp16(d + 18432, g_hL + so);
    }
#pragma unroll
    for (int f = 0; f < 2; f++) {
        int u = f*256 + t; int row = u >> 3, seg = u & 7;
        cp16(sb + 36864 + row*144 + seg*16,
             g_w1 + (size_t)(c0+row)*256 + koff + seg*8);
    }
}

__global__ void __launch_bounds__(256, 2) gemm1_mma() {
    extern __shared__ __align__(16) char smem[];
    const int t = threadIdx.x, wid = t >> 5, lane = t & 31;
    const int c0 = blockIdx.x * 64, m0 = blockIdx.y * 128;
    uint32_t sbase = smem_u32(smem);
    float acc[8][4];
#pragma unroll
    for (int j = 0; j < 8; j++)
#pragma unroll
        for (int i = 0; i < 4; i++) acc[j][i] = 0.f;

    g1_load(sbase, 0, 0, m0, c0);
    CP_COMMIT();

    const uint32_t aRow0 = (wid*16 + (lane & 15))*144 + (lane >> 4)*16;
    const int midx = lane >> 3;
    const int trow = (midx >> 1)*8 + (lane & 7);
    const int kh   = (midx & 1)*16;

    for (int ch = 0; ch < 4; ch++) {
        if (ch + 1 < 4) {
            g1_load(sbase, (ch + 1) & 1, ch + 1, m0, c0);
            CP_COMMIT();
            CP_WAIT(1);
        } else {
            CP_WAIT(0);
        }
        __syncthreads();
        uint32_t sb = sbase + (ch & 1)*G1_STAGE;
        uint32_t aRow = sb + aRow0;
#pragma unroll
        for (int kt = 0; kt < 4; kt++) {
            uint32_t ah0, ah1, ah2, ah3, al0, al1, al2, al3;
            ldsm_x4(ah0, ah1, ah2, ah3, aRow + kt*32);
            ldsm_x4(al0, al1, al2, al3, aRow + 18432 + kt*32);
#pragma unroll
            for (int jj = 0; jj < 4; jj++) {
                uint32_t ba = sb + 36864 + (jj*16 + trow)*144 + kt*32 + kh;
                uint32_t b0, b1, b2, b3;
                ldsm_x4(b0, b1, b2, b3, ba);
                mma_f16(acc[2*jj],   ah0, ah1, ah2, ah3, b0, b1);
                mma_f16(acc[2*jj+1], ah0, ah1, ah2, ah3, b2, b3);
                mma_f16(acc[2*jj],   al0, al1, al2, al3, b0, b1);
                mma_f16(acc[2*jj+1], al0, al1, al2, al3, b2, b3);
            }
        }
        __syncthreads();
    }
    const int r0 = m0 + wid*16 + (lane >> 2);
    const int cb = (lane & 3)*2;
#pragma unroll
    for (int j = 0; j < 8; j++) {
        int c = c0 + j*8 + cb;
        float2 bz = *(const float2*)&g_bias1[c];
#pragma unroll
        for (int hrow = 0; hrow < 2; hrow++) {
            int m = r0 + hrow*8;
            float v0 = acc[j][hrow*2]   + bz.x;
            float v1 = acc[j][hrow*2+1] + bz.y;
            __half h0, l0, h1, l1;
            h_split(v0, h0, l0); h_split(v1, h1, l1);
            *(__half2*)&g_hioH[(size_t)m*512 + c] = __halves2half2(h0, h1);
            *(__half2*)&g_hioL[(size_t)m*512 + c] = __halves2half2(l0, l1);
        }
    }
}

// ---------------- GEMM2 (fp16x3): inp = A_adj @ hio + bias --------------------
#define G2_A   0          // 2 planes x 64 x 144 = 18432
#define G2_B   18432      // 2 planes x 64 x 528 = 67584
#define G2_SMEM 86016

__global__ void __launch_bounds__(256, 2) gemm2_mma(const float* __restrict__ b_iah,
                                                    const float* __restrict__ b_oah) {
    extern __shared__ __align__(16) char smem[];
    const int t = threadIdx.x, wid = t >> 5, lane = t & 31;
    const int b = blockIdx.x, half_ = blockIdx.y;
    uint32_t sbase = smem_u32(smem);
    // load A: 2 planes x 64 rows x 8 segs
#pragma unroll
    for (int f = 0; f < 4; f++) {
        int u = f*256 + t; int pl = u >> 9, row = (u >> 3) & 63, seg = u & 7;
        const __half* src = pl ? g_AL : g_AH;
        cp16(sbase + G2_A + pl*9216 + row*144 + seg*16,
             src + (size_t)b*8192 + row*128 + half_*64 + seg*8);
    }
    // load hio tile: 2 planes x 64 rows x 32 segs
#pragma unroll
    for (int f = 0; f < 16; f++) {
        int u = f*256 + t; int pl = u >> 11, row = (u >> 5) & 63, seg = u & 31;
        const __half* src = pl ? g_hioL : g_hioH;
        cp16(sbase + G2_B + pl*33792 + row*528 + seg*16,
             src + ((size_t)b*64 + row)*512 + half_*256 + seg*8);
    }
    CP_COMMIT(); CP_WAIT(0);
    __syncthreads();

    const int wr = wid >> 2, wc = wid & 3;
    float acc[2][8][4];
#pragma unroll
    for (int r = 0; r < 2; r++)
#pragma unroll
        for (int j = 0; j < 8; j++)
#pragma unroll
            for (int i = 0; i < 4; i++) acc[r][j][i] = 0.f;

    uint32_t aBase = sbase + G2_A + (wr*32 + (lane & 15))*144 + (lane >> 4)*16;
#pragma unroll
    for (int kt = 0; kt < 4; kt++) {
        uint32_t ah[2][4], al[2][4];
#pragma unroll
        for (int r = 0; r < 2; r++) {
            ldsm_x4(ah[r][0], ah[r][1], ah[r][2], ah[r][3],
                    aBase + r*2304 + kt*32);
            ldsm_x4(al[r][0], al[r][1], al[r][2], al[r][3],
                    aBase + 9216 + r*2304 + kt*32);
        }
#pragma unroll
        for (int jj = 0; jj < 4; jj++) {
            uint32_t ba = sbase + G2_B + (kt*16 + (lane & 15))*528 +
                          (wc*64 + jj*16 + (lane >> 4)*8)*2;
            uint32_t bh0, bh1, bh2, bh3, bl0, bl1, bl2, bl3;
            ldsm_x4_t(bh0, bh1, bh2, bh3, ba);
            ldsm_x4_t(bl0, bl1, bl2, bl3, ba + 33792);
#pragma unroll
            for (int r = 0; r < 2; r++) {
                mma_f16(acc[r][jj*2],   ah[r][0], ah[r][1], ah[r][2], ah[r][3], bh0, bh1);
                mma_f16(acc[r][jj*2+1], ah[r][0], ah[r][1], ah[r][2], ah[r][3], bh2, bh3);
                mma_f16(acc[r][jj*2],   al[r][0], al[r][1], al[r][2], al[r][3], bh0, bh1);
                mma_f16(acc[r][jj*2+1], al[r][0], al[r][1], al[r][2], al[r][3], bh2, bh3);
                mma_f16(acc[r][jj*2],   ah[r][0], ah[r][1], ah[r][2], ah[r][3], bl0, bl1);
                mma_f16(acc[r][jj*2+1], ah[r][0], ah[r][1], ah[r][2], ah[r][3], bl2, bl3);
            }
        }
    }
    const float* bias = half_ ? b_oah : b_iah;
#pragma unroll
    for (int r = 0; r < 2; r++) {
        int n = wr*32 + r*16 + (lane >> 2);
#pragma unroll
        for (int j = 0; j < 8; j++) {
            int col = wc*64 + j*8 + (lane & 3)*2;
#pragma unroll
            for (int hrow = 0; hrow < 2; hrow++) {
                int nn = n + hrow*8;
                float v0 = acc[r][j][hrow*2]   + bias[col];
                float v1 = acc[r][j][hrow*2+1] + bias[col+1];
                size_t o = ((size_t)b*64 + nn)*512 + half_*256 + col;
                *(__half2*)&g_inpH[o] =
                    __halves2half2(__float2half_rn(v0), __float2half_rn(v1));
            }
        }
    }
}

// ---------------- GEMM3: gates + fused GRU ------------------------------------
// CTA 128 rows x 32 cols x 4 planes. gi chunks (0..7): A hi only (inp).
// gh chunks (8..11): A hi+lo (h).
#define G3_B     36864    // A hi 18432 + A lo 18432
#define G3_STAGE 50688    // + B 96 x 144 = 13824
#define G3_BIAS  (2*G3_STAGE)
#define G3_SMEM  (G3_BIAS + 768)

__device__ __forceinline__ void g3_load(uint32_t sbase, int st, int ch,
                                        int m0, int c0) {
    const int t = threadIdx.x;
    uint32_t sb = sbase + st*G3_STAGE;
    if (ch < 8) {
        int koff = ch*64;
#pragma unroll
        for (int f = 0; f < 4; f++) {
            int u = f*256 + t; int row = u >> 3, seg = u & 7;
            cp16(sb + row*144 + seg*16,
                 g_inpH + (size_t)(m0+row)*512 + koff + seg*8);
        }
#pragma unroll
        for (int f = 0; f < 3; f++) {
            int u = f*256 + t; int row = u >> 3, seg = u & 7;
            int g = row >> 5, n = row & 31;
            cp16(sb + G3_B + row*144 + seg*16,
                 g_wih + (size_t)(g*256 + c0 + n)*512 + koff + seg*8);
        }
    } else {
        int koff = (ch-8)*64;
#pragma unroll
        for (int f = 0; f < 4; f++) {
            int u = f*256 + t; int row = u >> 3, seg = u & 7;
            size_t so = (size_t)(m0+row)*256 + koff + seg*8;
            uint32_t d = sb + row*144 + seg*16;
            cp16(d,         g_hH + so);
            cp16(d + 18432, g_hL + so);
        }
#pragma unroll
        for (int f = 0; f < 3; f++) {
            int u = f*256 + t; int row = u >> 3, seg = u & 7;
            int g = row >> 5, n = row & 31;
            cp16(sb + G3_B + row*144 + seg*16,
                 g_whh + (size_t)(g*256 + c0 + n)*256 + koff + seg*8);
        }
    }
}

template<bool GH>
__device__ __forceinline__ void g3_mma_chunk(uint32_t sb, int wr, int wc, int lane,
                                             float (&acc)[4][2][2][4]) {
    uint32_t aBase = sb + (wr*32 + (lane & 15))*144 + (lane >> 4)*16;
    const int midx = lane >> 3;
    const int trow = (midx >> 1)*8 + (lane & 7);
    const int kh   = (midx & 1)*16;
#pragma unroll
    for (int kt = 0; kt < 4; kt++) {
        uint32_t a[2][2][4];
#pragma unroll
        for (int r = 0; r < 2; r++) {
            ldsm_x4(a[r][0][0], a[r][0][1], a[r][0][2], a[r][0][3],
                    aBase + r*2304 + kt*32);
            if (GH)
                ldsm_x4(a[r][1][0], a[r][1][1], a[r][1][2], a[r][1][3],
                        aBase + 18432 + r*2304 + kt*32);
        }
#pragma unroll
        for (int g = 0; g < 3; g++) {
            const int p = (!GH || g < 2) ? g : 3;
            uint32_t b0, b1, b2, b3;
            ldsm_x4(b0, b1, b2, b3,
                    sb + G3_B + (g*32 + wc*16 + trow)*144 + kt*32 + kh);
#pragma unroll
            for (int r = 0; r < 2; r++) {
#pragma unroll
                for (int s = 0; s < (GH ? 2 : 1); s++) {
                    mma_f16(acc[p][r][0], a[r][s][0], a[r][s][1],
                            a[r][s][2], a[r][s][3], b0, b1);
                    mma_f16(acc[p][r][1], a[r][s][0], a[r][s][1],
                            a[r][s][2], a[r][s][3], b2, b3);
                }
            }
        }
    }
}

__global__ void __launch_bounds__(256, 2) gemm3_mma(const float* __restrict__ b_ih,
                                                    const float* __restrict__ b_hh) {
    extern __shared__ __align__(16) char smem[];
    const int t = threadIdx.x, wid = t >> 5, lane = t & 31;
    const int c0 = blockIdx.x * 32, m0 = blockIdx.y * 128;
    const int wr = wid & 3, wc = wid >> 2;
    uint32_t sbase = smem_u32(smem);
    float* sbih = (float*)(smem + G3_BIAS);
    float* sbhh = (float*)(smem + G3_BIAS + 384);
    if (t < 32) {
#pragma unroll
        for (int g = 0; g < 3; g++) {
            sbih[g*32 + t] = b_ih[g*256 + c0 + t];
            sbhh[g*32 + t] = b_hh[g*256 + c0 + t];
        }
    }
    float acc[4][2][2][4];
#pragma unroll
    for (int p = 0; p < 4; p++)
#pragma unroll
        for (int r = 0; r < 2; r++)
#pragma unroll
            for (int cgi = 0; cgi < 2; cgi++)
#pragma unroll
                for (int i = 0; i < 4; i++) acc[p][r][cgi][i] = 0.f;

    g3_load(sbase, 0, 0, m0, c0);
    CP_COMMIT();

    for (int ch = 0; ch < 12; ch++) {
        if (ch + 1 < 12) {
            g3_load(sbase, (ch + 1) & 1, ch + 1, m0, c0);
            CP_COMMIT();
            CP_WAIT(1);
        } else {
            CP_WAIT(0);
        }
        __syncthreads();
        uint32_t sb = sbase + (ch & 1)*G3_STAGE;
        if (ch < 8) g3_mma_chunk<false>(sb, wr, wc, lane, acc);
        else        g3_mma_chunk<true >(sb, wr, wc, lane, acc);
        __syncthreads();
    }

    // GRU epilogue (h reconstructed from fp16 hi/lo pair)
    const int rbase = m0 + wr*32 + (lane >> 2);
    const int cb = (lane & 3)*2;
#pragma unroll
    for (int r = 0; r < 2; r++) {
#pragma unroll
        for (int cgi = 0; cgi < 2; cgi++) {
            int cl = wc*16 + cgi*8 + cb;
            int c  = c0 + cl;
#pragma unroll
            for (int hrow = 0; hrow < 2; hrow++) {
                int m = rbase + r*16 + hrow*8;
                __half2 hh = *(const __half2*)&g_hH[(size_t)m*256 + c];
                __half2 hl = *(const __half2*)&g_hL[(size_t)m*256 + c];
                float hv[2];
                hv[0] = __half2float(__low2half(hh)) + __half2float(__low2half(hl));
                hv[1] = __half2float(__high2half(hh)) + __half2float(__high2half(hl));
                float o[2];
#pragma unroll
                for (int e = 0; e < 2; e++) {
                    int li = cl + e;
                    int fi = hrow*2 + e;
                    float rr = 1.f/(1.f + expf(-(acc[0][r][cgi][fi] +
                                                 sbih[li] + sbhh[li])));
                    float zz = 1.f/(1.f + expf(-(acc[1][r][cgi][fi] +
                                                 sbih[32+li] + sbhh[32+li])));
                    float nn = tanhf(acc[2][r][cgi][fi] + sbih[64+li] +
                                     rr*(acc[3][r][cgi][fi] + sbhh[64+li]));
                    o[e] = nn + zz*(hv[e] - nn);
                }
                *(float2*)&g_hn[(size_t)m*256 + c] = make_float2(o[0], o[1]);
            }
        }
    }
}

// ---------------- attention / star update (hn cached in smem) -----------------
#define ATTN_SMEM ((16384 + 256 + 64 + 64 + 64) * 4)

__global__ void __launch_bounds__(256) attn(const float* __restrict__ mask,
                                            float* __restrict__ out,
                                            int final_) {
    extern __shared__ float sm[];
    float* s_hn    = sm;              // 64 x 256
    float* s_star  = sm + 16384;
    float* s_alpha = s_star + 256;
    float* s_v     = s_alpha + 64;
    float* s_p     = s_v + 64;
    int b = blockIdx.x, t = threadIdx.x, lane = t & 31, w = t >> 5;
    s_star[t] = g_star[(size_t)b*256 + t];
    const float4* src = (const float4*)&g_hn[(size_t)b*64*256];
    float4* dst = (float4*)s_hn;
#pragma unroll
    for (int f = 0; f < 16; f++) dst[f*256 + t] = src[f*256 + t];
    __syncthreads();
#pragma unroll
    for (int r = 0; r < 8; r++) {
        int n = w*8 + r;
        float p = 0.f;
#pragma unroll
        for (int j = lane; j < 256; j += 32) p += s_hn[n*256 + j] * s_star[j];
#pragma unroll
        for (int o = 16; o; o >>= 1) p += __shfl_xor_sync(0xffffffffu, p, o);
        if (lane == 0) s_v[n] = p;
    }
    __syncthreads();
    float ss = 0.f;
#pragma unroll 8
    for (int j = 0; j < 256; j++) { float x = s_star[j]; ss += x*x; }
    if (t < 64) {
        float sraw = s_v[t];
        float a = 1.f / (1.f + expf(-sraw * 0.0625f));
        s_alpha[t] = a;
        float d2 = (1.f - a)*sraw + a*ss;
        s_v[t] = expf(d2) * mask[(size_t)b*64 + t];
    }
    __syncthreads();
    float den = 1e-24f;
#pragma unroll
    for (int n = 0; n < 64; n++) den += s_v[n];
    if (t < 64) s_p[t] = s_v[t] / den;
    __syncthreads();
    float st = s_star[t];
    float accS = 0.f;
#pragma unroll 4
    for (int n = 0; n < 64; n++) {
        float a = s_alpha[n];
        size_t idx = ((size_t)b*64 + n)*256 + t;
        float h2 = (1.f - a)*s_hn[n*256 + t] + a*st;
        __half hi, lo; h_split(h2, hi, lo);
        g_hH[idx] = hi; g_hL[idx] = lo;
        if (final_) out[idx] = h2;
        accS += s_p[n] * h2;
    }
    g_star[(size_t)b*256 + t] = accS;
    if (final_) out[(size_t)Bb*Nn*Hh + (size_t)b*256 + t] = accS;
}

// ---------------- launch ------------------------------------------------------
extern "C" void kernel_launch(void* const* d_in, const int* in_sizes, int n_in,
                              void* d_out, int out_size) {
    const float* A      = (const float*)d_in[0];
    const float* hidden = (const float*)d_in[1];
    const float* mask   = (const float*)d_in[2];
    const float* w_ih   = (const float*)d_in[3];
    const float* w_hh   = (const float*)d_in[4];
    const float* b_ih   = (const float*)d_in[5];
    const float* b_hh   = (const float*)d_in[6];
    const float* b_iah  = (const float*)d_in[7];
    const float* b_oah  = (const float*)d_in[8];
    const float* W_in   = (const float*)d_in[9];
    const float* b_in   = (const float*)d_in[10];
    const float* W_out  = (const float*)d_in[11];
    const float* b_out  = (const float*)d_in[12];
    float* out = (float*)d_out;

    cudaFuncSetAttribute(gemm1_mma, cudaFuncAttributeMaxDynamicSharedMemorySize, G1_SMEM);
    cudaFuncSetAttribute(gemm2_mma, cudaFuncAttributeMaxDynamicSharedMemorySize, G2_SMEM);
    cudaFuncSetAttribute(gemm3_mma, cudaFuncAttributeMaxDynamicSharedMemorySize, G3_SMEM);
    cudaFuncSetAttribute(attn,      cudaFuncAttributeMaxDynamicSharedMemorySize, ATTN_SMEM);

    setup_weights<<<1536, 256>>>(W_in, b_in, W_out, b_out, w_ih, w_hh);
    setup_A<<<4096, 256>>>(A);
    init_h<<<Bb, 256>>>(hidden, mask);

    for (int s = 0; s < 2; s++) {
        gemm1_mma<<<dim3(8, 1024), 256, G1_SMEM>>>();
        gemm2_mma<<<dim3(Bb, 2), 256, G2_SMEM>>>(b_iah, b_oah);
        gemm3_mma<<<dim3(8, 1024), 256, G3_SMEM>>>(b_ih, b_hh);
        attn<<<Bb, 256, ATTN_SMEM>>>(mask, out, s == 1);
    }
}

// round 8
// speedup vs baseline: 4.9204x; 1.1357x over previous
#include <cuda_runtime.h>
#include <cuda_fp16.h>
#include <math.h>
#include <cstdint>

#define Bb   2048
#define Nn   64
#define Hh   256
#define MTOT (Bb*Nn)          // 131072

// ---------------- scratch (static device globals; no allocations) ----------
__device__ float g_hn  [MTOT*Hh];         // hidden after GRU cell (fp32)
__device__ float g_star[Bb*Hh];
__device__ float g_bias1[512];
// fp16 split activations / rounded weights
__device__ __half g_hH  [MTOT*256];
__device__ __half g_hL  [MTOT*256];       // epilogue-only (exact h reconstruction)
__device__ __half g_hioH[MTOT*512];
__device__ __half g_hioL[MTOT*512];
__device__ __half g_inpH[MTOT*512];
__device__ __half g_AH  [Bb*64*128];
__device__ __half g_AL  [Bb*64*128];
__device__ __half g_w1  [512*256];        // [c][k]: c<256 W_in, else W_out
__device__ __half g_wih [768*512];        // [n][k]
__device__ __half g_whh [768*256];

// ---------------- helpers ----------------------------------------------------
__device__ __forceinline__ uint32_t smem_u32(const void* p) {
    uint32_t a;
    asm("{ .reg .u64 t; cvta.to.shared.u64 t, %1; cvt.u32.u64 %0, t; }"
        : "=r"(a) : "l"(p));
    return a;
}
__device__ __forceinline__ void cp16(uint32_t dst, const void* src) {
    asm volatile("cp.async.cg.shared.global [%0], [%1], 16;"
                 :: "r"(dst), "l"(src) : "memory");
}
#define CP_COMMIT() asm volatile("cp.async.commit_group;" ::: "memory")
#define CP_WAIT(n)  asm volatile("cp.async.wait_group %0;" :: "n"(n) : "memory")

__device__ __forceinline__ void ldsm_x4(uint32_t& r0, uint32_t& r1,
                                        uint32_t& r2, uint32_t& r3,
                                        uint32_t addr) {
    asm volatile("ldmatrix.sync.aligned.m8n8.x4.shared.b16 {%0,%1,%2,%3}, [%4];"
                 : "=r"(r0), "=r"(r1), "=r"(r2), "=r"(r3) : "r"(addr));
}
__device__ __forceinline__ void ldsm_x4_t(uint32_t& r0, uint32_t& r1,
                                          uint32_t& r2, uint32_t& r3,
                                          uint32_t addr) {
    asm volatile("ldmatrix.sync.aligned.m8n8.x4.trans.shared.b16 {%0,%1,%2,%3}, [%4];"
                 : "=r"(r0), "=r"(r1), "=r"(r2), "=r"(r3) : "r"(addr));
}
__device__ __forceinline__ void mma_f16(float* d,
                                        uint32_t a0, uint32_t a1,
                                        uint32_t a2, uint32_t a3,
                                        uint32_t b0, uint32_t b1) {
    asm volatile(
        "mma.sync.aligned.m16n8k16.row.col.f32.f16.f16.f32 "
        "{%0,%1,%2,%3}, {%4,%5,%6,%7}, {%8,%9}, {%0,%1,%2,%3};"
        : "+f"(d[0]), "+f"(d[1]), "+f"(d[2]), "+f"(d[3])
        : "r"(a0), "r"(a1), "r"(a2), "r"(a3), "r"(b0), "r"(b1));
}
__device__ __forceinline__ void h_split(float v, __half& hi, __half& lo) {
    hi = __float2half_rn(v);
    lo = __float2half_rn(v - __half2float(hi));
}

// ---------------- setup -------------------------------------------------------
__global__ void setup_weights(const float* __restrict__ W_in,
                              const float* __restrict__ b_in,
                              const float* __restrict__ W_out,
                              const float* __restrict__ b_out,
                              const float* __restrict__ w_ih,
                              const float* __restrict__ w_hh) {
    int i = blockIdx.x * blockDim.x + threadIdx.x;
    if (i < 512) g_bias1[i] = (i < 256) ? b_in[i] : b_out[i-256];
    if (i < 512*256) {
        int c = i >> 8, k = i & 255;
        float v = (c < 256) ? W_in[c*256 + k] : W_out[(c-256)*256 + k];
        g_w1[i] = __float2half_rn(v);
    }
    if (i < 768*512) g_wih[i] = __float2half_rn(w_ih[i]);
    if (i < 768*256) g_whh[i] = __float2half_rn(w_hh[i]);
}

__global__ void setup_A(const float* __restrict__ A) {
    size_t n = (size_t)Bb*64*128;
    for (size_t i = blockIdx.x*(size_t)blockDim.x + threadIdx.x; i < n;
         i += (size_t)gridDim.x*blockDim.x) {
        __half hi, lo; h_split(A[i], hi, lo);
        g_AH[i] = hi; g_AL[i] = lo;
    }
}

// fused: split hidden into hH/hL + compute star (masked mean)
__global__ void __launch_bounds__(256) init_h(const float* __restrict__ hidden,
                                              const float* __restrict__ mask) {
    int b = blockIdx.x, t = threadIdx.x;
    float len = 0.f, acc = 0.f;
#pragma unroll 4
    for (int n = 0; n < 64; n++) {
        float mk = mask[b*64 + n];
        size_t idx = ((size_t)b*64 + n)*256 + t;
        float v = hidden[idx];
        __half hi, lo; h_split(v, hi, lo);
        g_hH[idx] = hi; g_hL[idx] = lo;
        acc += v * mk; len += mk;
    }
    g_star[(size_t)b*256 + t] = acc / len;
}

// ---------------- GEMM1 (fp16): hio = h @ [W_in^T|W_out^T] + bias ------------
#define G1_STAGE 27648   // A hi 18432 + B 9216
#define G1_SMEM  (2*G1_STAGE)

__device__ __forceinline__ void g1_load(uint32_t sbase, int st, int ch,
                                        int m0, int c0) {
    const int t = threadIdx.x;
    uint32_t sb = sbase + st*G1_STAGE;
    int koff = ch*64;
#pragma unroll
    for (int f = 0; f < 4; f++) {
        int u = f*256 + t; int row = u >> 3, seg = u & 7;
        cp16(sb + row*144 + seg*16,
             g_hH + (size_t)(m0+row)*256 + koff + seg*8);
    }
#pragma unroll
    for (int f = 0; f < 2; f++) {
        int u = f*256 + t; int row = u >> 3, seg = u & 7;
        cp16(sb + 18432 + row*144 + seg*16,
             g_w1 + (size_t)(c0+row)*256 + koff + seg*8);
    }
}

__global__ void __launch_bounds__(256, 2) gemm1_mma() {
    extern __shared__ __align__(16) char smem[];
    const int t = threadIdx.x, wid = t >> 5, lane = t & 31;
    const int c0 = blockIdx.x * 64, m0 = blockIdx.y * 128;
    uint32_t sbase = smem_u32(smem);
    float acc[8][4];
#pragma unroll
    for (int j = 0; j < 8; j++)
#pragma unroll
        for (int i = 0; i < 4; i++) acc[j][i] = 0.f;

    g1_load(sbase, 0, 0, m0, c0);
    CP_COMMIT();

    const uint32_t aRow0 = (wid*16 + (lane & 15))*144 + (lane >> 4)*16;
    const int midx = lane >> 3;
    const int trow = (midx >> 1)*8 + (lane & 7);
    const int kh   = (midx & 1)*16;

    for (int ch = 0; ch < 4; ch++) {
        if (ch + 1 < 4) {
            g1_load(sbase, (ch + 1) & 1, ch + 1, m0, c0);
            CP_COMMIT();
            CP_WAIT(1);
        } else {
            CP_WAIT(0);
        }
        __syncthreads();
        uint32_t sb = sbase + (ch & 1)*G1_STAGE;
        uint32_t aRow = sb + aRow0;
#pragma unroll
        for (int kt = 0; kt < 4; kt++) {
            uint32_t a0, a1, a2, a3;
            ldsm_x4(a0, a1, a2, a3, aRow + kt*32);
#pragma unroll
            for (int jj = 0; jj < 4; jj++) {
                uint32_t ba = sb + 18432 + (jj*16 + trow)*144 + kt*32 + kh;
                uint32_t b0, b1, b2, b3;
                ldsm_x4(b0, b1, b2, b3, ba);
                mma_f16(acc[2*jj],   a0, a1, a2, a3, b0, b1);
                mma_f16(acc[2*jj+1], a0, a1, a2, a3, b2, b3);
            }
        }
        __syncthreads();
    }
    const int r0 = m0 + wid*16 + (lane >> 2);
    const int cb = (lane & 3)*2;
#pragma unroll
    for (int j = 0; j < 8; j++) {
        int c = c0 + j*8 + cb;
        float2 bz = *(const float2*)&g_bias1[c];
#pragma unroll
        for (int hrow = 0; hrow < 2; hrow++) {
            int m = r0 + hrow*8;
            float v0 = acc[j][hrow*2]   + bz.x;
            float v1 = acc[j][hrow*2+1] + bz.y;
            __half h0, l0, h1, l1;
            h_split(v0, h0, l0); h_split(v1, h1, l1);
            *(__half2*)&g_hioH[(size_t)m*512 + c] = __halves2half2(h0, h1);
            *(__half2*)&g_hioL[(size_t)m*512 + c] = __halves2half2(l0, l1);
        }
    }
}

// ---------------- GEMM2 (fp16x3): inp = A_adj @ hio + bias --------------------
#define G2_A   0          // 2 planes x 64 x 144 = 18432
#define G2_B   18432      // 2 planes x 64 x 528 = 67584
#define G2_SMEM 86016

__global__ void __launch_bounds__(256, 2) gemm2_mma(const float* __restrict__ b_iah,
                                                    const float* __restrict__ b_oah) {
    extern __shared__ __align__(16) char smem[];
    const int t = threadIdx.x, wid = t >> 5, lane = t & 31;
    const int b = blockIdx.x, half_ = blockIdx.y;
    uint32_t sbase = smem_u32(smem);
    // load A: 2 planes x 64 rows x 8 segs
#pragma unroll
    for (int f = 0; f < 4; f++) {
        int u = f*256 + t; int pl = u >> 9, row = (u >> 3) & 63, seg = u & 7;
        const __half* src = pl ? g_AL : g_AH;
        cp16(sbase + G2_A + pl*9216 + row*144 + seg*16,
             src + (size_t)b*8192 + row*128 + half_*64 + seg*8);
    }
    // load hio tile: 2 planes x 64 rows x 32 segs
#pragma unroll
    for (int f = 0; f < 16; f++) {
        int u = f*256 + t; int pl = u >> 11, row = (u >> 5) & 63, seg = u & 31;
        const __half* src = pl ? g_hioL : g_hioH;
        cp16(sbase + G2_B + pl*33792 + row*528 + seg*16,
             src + ((size_t)b*64 + row)*512 + half_*256 + seg*8);
    }
    CP_COMMIT(); CP_WAIT(0);
    __syncthreads();

    const int wr = wid >> 2, wc = wid & 3;
    float acc[2][8][4];
#pragma unroll
    for (int r = 0; r < 2; r++)
#pragma unroll
        for (int j = 0; j < 8; j++)
#pragma unroll
            for (int i = 0; i < 4; i++) acc[r][j][i] = 0.f;

    uint32_t aBase = sbase + G2_A + (wr*32 + (lane & 15))*144 + (lane >> 4)*16;
#pragma unroll
    for (int kt = 0; kt < 4; kt++) {
        uint32_t ah[2][4], al[2][4];
#pragma unroll
        for (int r = 0; r < 2; r++) {
            ldsm_x4(ah[r][0], ah[r][1], ah[r][2], ah[r][3],
                    aBase + r*2304 + kt*32);
            ldsm_x4(al[r][0], al[r][1], al[r][2], al[r][3],
                    aBase + 9216 + r*2304 + kt*32);
        }
#pragma unroll
        for (int jj = 0; jj < 4; jj++) {
            uint32_t ba = sbase + G2_B + (kt*16 + (lane & 15))*528 +
                          (wc*64 + jj*16 + (lane >> 4)*8)*2;
            uint32_t bh0, bh1, bh2, bh3, bl0, bl1, bl2, bl3;
            ldsm_x4_t(bh0, bh1, bh2, bh3, ba);
            ldsm_x4_t(bl0, bl1, bl2, bl3, ba + 33792);
#pragma unroll
            for (int r = 0; r < 2; r++) {
                mma_f16(acc[r][jj*2],   ah[r][0], ah[r][1], ah[r][2], ah[r][3], bh0, bh1);
                mma_f16(acc[r][jj*2+1], ah[r][0], ah[r][1], ah[r][2], ah[r][3], bh2, bh3);
                mma_f16(acc[r][jj*2],   al[r][0], al[r][1], al[r][2], al[r][3], bh0, bh1);
                mma_f16(acc[r][jj*2+1], al[r][0], al[r][1], al[r][2], al[r][3], bh2, bh3);
                mma_f16(acc[r][jj*2],   ah[r][0], ah[r][1], ah[r][2], ah[r][3], bl0, bl1);
                mma_f16(acc[r][jj*2+1], ah[r][0], ah[r][1], ah[r][2], ah[r][3], bl2, bl3);
            }
        }
    }
    const float* bias = half_ ? b_oah : b_iah;
#pragma unroll
    for (int r = 0; r < 2; r++) {
        int n = wr*32 + r*16 + (lane >> 2);
#pragma unroll
        for (int j = 0; j < 8; j++) {
            int col = wc*64 + j*8 + (lane & 3)*2;
#pragma unroll
            for (int hrow = 0; hrow < 2; hrow++) {
                int nn = n + hrow*8;
                float v0 = acc[r][j][hrow*2]   + bias[col];
                float v1 = acc[r][j][hrow*2+1] + bias[col+1];
                size_t o = ((size_t)b*64 + nn)*512 + half_*256 + col;
                *(__half2*)&g_inpH[o] =
                    __halves2half2(__float2half_rn(v0), __float2half_rn(v1));
            }
        }
    }
}

// ---------------- GEMM3: gates + fused GRU ------------------------------------
// CTA 128 rows x 32 cols x 4 planes. All chunks: A hi only.
#define G3_B     18432    // A hi
#define G3_STAGE 32256    // + B 96 x 144 = 13824
#define G3_BIAS  (2*G3_STAGE)
#define G3_SMEM  (G3_BIAS + 768)

__device__ __forceinline__ void g3_load(uint32_t sbase, int st, int ch,
                                        int m0, int c0) {
    const int t = threadIdx.x;
    uint32_t sb = sbase + st*G3_STAGE;
    const __half *Ah, *Bw; int ak, koff;
    if (ch < 8) { Ah = g_inpH; Bw = g_wih; ak = 512; koff = ch*64; }
    else        { Ah = g_hH;   Bw = g_whh; ak = 256; koff = (ch-8)*64; }
#pragma unroll
    for (int f = 0; f < 4; f++) {
        int u = f*256 + t; int row = u >> 3, seg = u & 7;
        cp16(sb + row*144 + seg*16,
             Ah + (size_t)(m0+row)*ak + koff + seg*8);
    }
#pragma unroll
    for (int f = 0; f < 3; f++) {
        int u = f*256 + t; int row = u >> 3, seg = u & 7;
        int g = row >> 5, n = row & 31;
        cp16(sb + G3_B + row*144 + seg*16,
             Bw + (size_t)(g*256 + c0 + n)*ak + koff + seg*8);
    }
}

template<bool GH>
__device__ __forceinline__ void g3_mma_chunk(uint32_t sb, int wr, int wc, int lane,
                                             float (&acc)[4][2][2][4]) {
    uint32_t aBase = sb + (wr*32 + (lane & 15))*144 + (lane >> 4)*16;
    const int midx = lane >> 3;
    const int trow = (midx >> 1)*8 + (lane & 7);
    const int kh   = (midx & 1)*16;
#pragma unroll
    for (int kt = 0; kt < 4; kt++) {
        uint32_t a[2][4];
#pragma unroll
        for (int r = 0; r < 2; r++)
            ldsm_x4(a[r][0], a[r][1], a[r][2], a[r][3],
                    aBase + r*2304 + kt*32);
#pragma unroll
        for (int g = 0; g < 3; g++) {
            const int p = (!GH || g < 2) ? g : 3;
            uint32_t b0, b1, b2, b3;
            ldsm_x4(b0, b1, b2, b3,
                    sb + G3_B + (g*32 + wc*16 + trow)*144 + kt*32 + kh);
#pragma unroll
            for (int r = 0; r < 2; r++) {
                mma_f16(acc[p][r][0], a[r][0], a[r][1], a[r][2], a[r][3], b0, b1);
                mma_f16(acc[p][r][1], a[r][0], a[r][1], a[r][2], a[r][3], b2, b3);
            }
        }
    }
}

__global__ void __launch_bounds__(256, 2) gemm3_mma(const float* __restrict__ b_ih,
                                                    const float* __restrict__ b_hh) {
    extern __shared__ __align__(16) char smem[];
    const int t = threadIdx.x, wid = t >> 5, lane = t & 31;
    const int c0 = blockIdx.x * 32, m0 = blockIdx.y * 128;
    const int wr = wid & 3, wc = wid >> 2;
    uint32_t sbase = smem_u32(smem);
    float* sbih = (float*)(smem + G3_BIAS);
    float* sbhh = (float*)(smem + G3_BIAS + 384);
    if (t < 32) {
#pragma unroll
        for (int g = 0; g < 3; g++) {
            sbih[g*32 + t] = b_ih[g*256 + c0 + t];
            sbhh[g*32 + t] = b_hh[g*256 + c0 + t];
        }
    }
    float acc[4][2][2][4];
#pragma unroll
    for (int p = 0; p < 4; p++)
#pragma unroll
        for (int r = 0; r < 2; r++)
#pragma unroll
            for (int cgi = 0; cgi < 2; cgi++)
#pragma unroll
                for (int i = 0; i < 4; i++) acc[p][r][cgi][i] = 0.f;

    g3_load(sbase, 0, 0, m0, c0);
    CP_COMMIT();

    for (int ch = 0; ch < 12; ch++) {
        if (ch + 1 < 12) {
            g3_load(sbase, (ch + 1) & 1, ch + 1, m0, c0);
            CP_COMMIT();
            CP_WAIT(1);
        } else {
            CP_WAIT(0);
        }
        __syncthreads();
        uint32_t sb = sbase + (ch & 1)*G3_STAGE;
        if (ch < 8) g3_mma_chunk<false>(sb, wr, wc, lane, acc);
        else        g3_mma_chunk<true >(sb, wr, wc, lane, acc);
        __syncthreads();
    }

    // GRU epilogue (h reconstructed exactly from fp16 hi/lo pair)
    const int rbase = m0 + wr*32 + (lane >> 2);
    const int cb = (lane & 3)*2;
#pragma unroll
    for (int r = 0; r < 2; r++) {
#pragma unroll
        for (int cgi = 0; cgi < 2; cgi++) {
            int cl = wc*16 + cgi*8 + cb;
            int c  = c0 + cl;
#pragma unroll
            for (int hrow = 0; hrow < 2; hrow++) {
                int m = rbase + r*16 + hrow*8;
                __half2 hh = *(const __half2*)&g_hH[(size_t)m*256 + c];
                __half2 hl = *(const __half2*)&g_hL[(size_t)m*256 + c];
                float hv[2];
                hv[0] = __half2float(__low2half(hh)) + __half2float(__low2half(hl));
                hv[1] = __half2float(__high2half(hh)) + __half2float(__high2half(hl));
                float o[2];
#pragma unroll
                for (int e = 0; e < 2; e++) {
                    int li = cl + e;
                    int fi = hrow*2 + e;
                    float rr = 1.f/(1.f + expf(-(acc[0][r][cgi][fi] +
                                                 sbih[li] + sbhh[li])));
                    float zz = 1.f/(1.f + expf(-(acc[1][r][cgi][fi] +
                                                 sbih[32+li] + sbhh[32+li])));
                    float nn = tanhf(acc[2][r][cgi][fi] + sbih[64+li] +
                                     rr*(acc[3][r][cgi][fi] + sbhh[64+li]));
                    o[e] = nn + zz*(hv[e] - nn);
                }
                *(float2*)&g_hn[(size_t)m*256 + c] = make_float2(o[0], o[1]);
            }
        }
    }
}

// ---------------- attention / star update (hn cached in smem) -----------------
#define ATTN_SMEM ((16384 + 256 + 64 + 64 + 64) * 4)

__global__ void __launch_bounds__(256) attn(const float* __restrict__ mask,
                                            float* __restrict__ out,
                                            int final_) {
    extern __shared__ float sm[];
    float* s_hn    = sm;              // 64 x 256
    float* s_star  = sm + 16384;
    float* s_alpha = s_star + 256;
    float* s_v     = s_alpha + 64;
    float* s_p     = s_v + 64;
    int b = blockIdx.x, t = threadIdx.x, lane = t & 31, w = t >> 5;
    s_star[t] = g_star[(size_t)b*256 + t];
    const float4* src = (const float4*)&g_hn[(size_t)b*64*256];
    float4* dst = (float4*)s_hn;
#pragma unroll
    for (int f = 0; f < 16; f++) dst[f*256 + t] = src[f*256 + t];
    __syncthreads();
#pragma unroll
    for (int r = 0; r < 8; r++) {
        int n = w*8 + r;
        float p = 0.f;
#pragma unroll
        for (int j = lane; j < 256; j += 32) p += s_hn[n*256 + j] * s_star[j];
#pragma unroll
        for (int o = 16; o; o >>= 1) p += __shfl_xor_sync(0xffffffffu, p, o);
        if (lane == 0) s_v[n] = p;
    }
    __syncthreads();
    float ss = 0.f;
#pragma unroll 8
    for (int j = 0; j < 256; j++) { float x = s_star[j]; ss += x*x; }
    if (t < 64) {
        float sraw = s_v[t];
        float a = 1.f / (1.f + expf(-sraw * 0.0625f));
        s_alpha[t] = a;
        float d2 = (1.f - a)*sraw + a*ss;
        s_v[t] = expf(d2) * mask[(size_t)b*64 + t];
    }
    __syncthreads();
    float den = 1e-24f;
#pragma unroll
    for (int n = 0; n < 64; n++) den += s_v[n];
    if (t < 64) s_p[t] = s_v[t] / den;
    __syncthreads();
    float st = s_star[t];
    float accS = 0.f;
#pragma unroll 4
    for (int n = 0; n < 64; n++) {
        float a = s_alpha[n];
        size_t idx = ((size_t)b*64 + n)*256 + t;
        float h2 = (1.f - a)*s_hn[n*256 + t] + a*st;
        __half hi, lo; h_split(h2, hi, lo);
        g_hH[idx] = hi; g_hL[idx] = lo;
        if (final_) out[idx] = h2;
        accS += s_p[n] * h2;
    }
    g_star[(size_t)b*256 + t] = accS;
    if (final_) out[(size_t)Bb*Nn*Hh + (size_t)b*256 + t] = accS;
}

// ---------------- launch ------------------------------------------------------
extern "C" void kernel_launch(void* const* d_in, const int* in_sizes, int n_in,
                              void* d_out, int out_size) {
    const float* A      = (const float*)d_in[0];
    const float* hidden = (const float*)d_in[1];
    const float* mask   = (const float*)d_in[2];
    const float* w_ih   = (const float*)d_in[3];
    const float* w_hh   = (const float*)d_in[4];
    const float* b_ih   = (const float*)d_in[5];
    const float* b_hh   = (const float*)d_in[6];
    const float* b_iah  = (const float*)d_in[7];
    const float* b_oah  = (const float*)d_in[8];
    const float* W_in   = (const float*)d_in[9];
    const float* b_in   = (const float*)d_in[10];
    const float* W_out  = (const float*)d_in[11];
    const float* b_out  = (const float*)d_in[12];
    float* out = (float*)d_out;

    cudaFuncSetAttribute(gemm1_mma, cudaFuncAttributeMaxDynamicSharedMemorySize, G1_SMEM);
    cudaFuncSetAttribute(gemm2_mma, cudaFuncAttributeMaxDynamicSharedMemorySize, G2_SMEM);
    cudaFuncSetAttribute(gemm3_mma, cudaFuncAttributeMaxDynamicSharedMemorySize, G3_SMEM);
    cudaFuncSetAttribute(attn,      cudaFuncAttributeMaxDynamicSharedMemorySize, ATTN_SMEM);

    setup_weights<<<1536, 256>>>(W_in, b_in, W_out, b_out, w_ih, w_hh);
    setup_A<<<4096, 256>>>(A);
    init_h<<<Bb, 256>>>(hidden, mask);

    for (int s = 0; s < 2; s++) {
        gemm1_mma<<<dim3(8, 1024), 256, G1_SMEM>>>();
        gemm2_mma<<<dim3(Bb, 2), 256, G2_SMEM>>>(b_iah, b_oah);
        gemm3_mma<<<dim3(8, 1024), 256, G3_SMEM>>>(b_ih, b_hh);
        attn<<<Bb, 256, ATTN_SMEM>>>(mask, out, s == 1);
    }
}

// round 9
// speedup vs baseline: 5.1753x; 1.0518x over previous
#include <cuda_runtime.h>
#include <cuda_fp16.h>
#include <math.h>
#include <cstdint>

#define Bb   2048
#define Nn   64
#define Hh   256
#define MTOT (Bb*Nn)          // 131072

// ---------------- scratch (static device globals; no allocations) ----------
__device__ float g_hn  [MTOT*Hh];         // hidden after GRU cell (fp32)
__device__ float g_star[Bb*Hh];
__device__ float g_bias1[512];
// fp16 split activations / rounded weights
__device__ __half g_hH  [MTOT*256];
__device__ __half g_hL  [MTOT*256];       // epilogue-only (exact h reconstruction)
__device__ __half g_hioH[MTOT*512];
__device__ __half g_inpH[MTOT*512];
__device__ __half g_AH  [Bb*64*128];
__device__ __half g_AL  [Bb*64*128];
__device__ __half g_w1  [512*256];        // [c][k]: c<256 W_in, else W_out
__device__ __half g_wih [768*512];        // [n][k]
__device__ __half g_whh [768*256];

// ---------------- helpers ----------------------------------------------------
__device__ __forceinline__ uint32_t smem_u32(const void* p) {
    uint32_t a;
    asm("{ .reg .u64 t; cvta.to.shared.u64 t, %1; cvt.u32.u64 %0, t; }"
        : "=r"(a) : "l"(p));
    return a;
}
__device__ __forceinline__ void cp16(uint32_t dst, const void* src) {
    asm volatile("cp.async.cg.shared.global [%0], [%1], 16;"
                 :: "r"(dst), "l"(src) : "memory");
}
#define CP_COMMIT() asm volatile("cp.async.commit_group;" ::: "memory")
#define CP_WAIT(n)  asm volatile("cp.async.wait_group %0;" :: "n"(n) : "memory")

__device__ __forceinline__ void ldsm_x4(uint32_t& r0, uint32_t& r1,
                                        uint32_t& r2, uint32_t& r3,
                                        uint32_t addr) {
    asm volatile("ldmatrix.sync.aligned.m8n8.x4.shared.b16 {%0,%1,%2,%3}, [%4];"
                 : "=r"(r0), "=r"(r1), "=r"(r2), "=r"(r3) : "r"(addr));
}
__device__ __forceinline__ void ldsm_x4_t(uint32_t& r0, uint32_t& r1,
                                          uint32_t& r2, uint32_t& r3,
                                          uint32_t addr) {
    asm volatile("ldmatrix.sync.aligned.m8n8.x4.trans.shared.b16 {%0,%1,%2,%3}, [%4];"
                 : "=r"(r0), "=r"(r1), "=r"(r2), "=r"(r3) : "r"(addr));
}
__device__ __forceinline__ void mma_f16(float* d,
                                        uint32_t a0, uint32_t a1,
                                        uint32_t a2, uint32_t a3,
                                        uint32_t b0, uint32_t b1) {
    asm volatile(
        "mma.sync.aligned.m16n8k16.row.col.f32.f16.f16.f32 "
        "{%0,%1,%2,%3}, {%4,%5,%6,%7}, {%8,%9}, {%0,%1,%2,%3};"
        : "+f"(d[0]), "+f"(d[1]), "+f"(d[2]), "+f"(d[3])
        : "r"(a0), "r"(a1), "r"(a2), "r"(a3), "r"(b0), "r"(b1));
}
__device__ __forceinline__ void h_split(float v, __half& hi, __half& lo) {
    hi = __float2half_rn(v);
    lo = __float2half_rn(v - __half2float(hi));
}

// ---------------- setup -------------------------------------------------------
__global__ void setup_weights(const float* __restrict__ W_in,
                              const float* __restrict__ b_in,
                              const float* __restrict__ W_out,
                              const float* __restrict__ b_out,
                              const float* __restrict__ w_ih,
                              const float* __restrict__ w_hh) {
    int i = blockIdx.x * blockDim.x + threadIdx.x;
    if (i < 512) g_bias1[i] = (i < 256) ? b_in[i] : b_out[i-256];
    if (i < 512*256) {
        int c = i >> 8, k = i & 255;
        float v = (c < 256) ? W_in[c*256 + k] : W_out[(c-256)*256 + k];
        g_w1[i] = __float2half_rn(v);
    }
    if (i < 768*512) g_wih[i] = __float2half_rn(w_ih[i]);
    if (i < 768*256) g_whh[i] = __float2half_rn(w_hh[i]);
}

__global__ void setup_A(const float* __restrict__ A) {
    size_t n = (size_t)Bb*64*128;
    for (size_t i = blockIdx.x*(size_t)blockDim.x + threadIdx.x; i < n;
         i += (size_t)gridDim.x*blockDim.x) {
        __half hi, lo; h_split(A[i], hi, lo);
        g_AH[i] = hi; g_AL[i] = lo;
    }
}

// fused: split hidden into hH/hL + compute star (masked mean)
__global__ void __launch_bounds__(256) init_h(const float* __restrict__ hidden,
                                              const float* __restrict__ mask) {
    int b = blockIdx.x, t = threadIdx.x;
    float len = 0.f, acc = 0.f;
#pragma unroll 4
    for (int n = 0; n < 64; n++) {
        float mk = mask[b*64 + n];
        size_t idx = ((size_t)b*64 + n)*256 + t;
        float v = hidden[idx];
        __half hi, lo; h_split(v, hi, lo);
        g_hH[idx] = hi; g_hL[idx] = lo;
        acc += v * mk; len += mk;
    }
    g_star[(size_t)b*256 + t] = acc / len;
}

// ---------------- GEMM1 (fp16): hio = h @ [W_in^T|W_out^T] + bias ------------
#define G1_STAGE 27648   // A hi 18432 + B 9216
#define G1_SMEM  (2*G1_STAGE)

__device__ __forceinline__ void g1_load(uint32_t sbase, int st, int ch,
                                        int m0, int c0) {
    const int t = threadIdx.x;
    uint32_t sb = sbase + st*G1_STAGE;
    int koff = ch*64;
#pragma unroll
    for (int f = 0; f < 4; f++) {
        int u = f*256 + t; int row = u >> 3, seg = u & 7;
        cp16(sb + row*144 + seg*16,
             g_hH + (size_t)(m0+row)*256 + koff + seg*8);
    }
#pragma unroll
    for (int f = 0; f < 2; f++) {
        int u = f*256 + t; int row = u >> 3, seg = u & 7;
        cp16(sb + 18432 + row*144 + seg*16,
             g_w1 + (size_t)(c0+row)*256 + koff + seg*8);
    }
}

__global__ void __launch_bounds__(256, 2) gemm1_mma() {
    extern __shared__ __align__(16) char smem[];
    const int t = threadIdx.x, wid = t >> 5, lane = t & 31;
    const int c0 = blockIdx.x * 64, m0 = blockIdx.y * 128;
    uint32_t sbase = smem_u32(smem);
    float acc[8][4];
#pragma unroll
    for (int j = 0; j < 8; j++)
#pragma unroll
        for (int i = 0; i < 4; i++) acc[j][i] = 0.f;

    g1_load(sbase, 0, 0, m0, c0);
    CP_COMMIT();

    const uint32_t aRow0 = (wid*16 + (lane & 15))*144 + (lane >> 4)*16;
    const int midx = lane >> 3;
    const int trow = (midx >> 1)*8 + (lane & 7);
    const int kh   = (midx & 1)*16;

    for (int ch = 0; ch < 4; ch++) {
        if (ch + 1 < 4) {
            g1_load(sbase, (ch + 1) & 1, ch + 1, m0, c0);
            CP_COMMIT();
            CP_WAIT(1);
        } else {
            CP_WAIT(0);
        }
        __syncthreads();
        uint32_t sb = sbase + (ch & 1)*G1_STAGE;
        uint32_t aRow = sb + aRow0;
#pragma unroll
        for (int kt = 0; kt < 4; kt++) {
            uint32_t a0, a1, a2, a3;
            ldsm_x4(a0, a1, a2, a3, aRow + kt*32);
#pragma unroll
            for (int jj = 0; jj < 4; jj++) {
                uint32_t ba = sb + 18432 + (jj*16 + trow)*144 + kt*32 + kh;
                uint32_t b0, b1, b2, b3;
                ldsm_x4(b0, b1, b2, b3, ba);
                mma_f16(acc[2*jj],   a0, a1, a2, a3, b0, b1);
                mma_f16(acc[2*jj+1], a0, a1, a2, a3, b2, b3);
            }
        }
        __syncthreads();
    }
    const int r0 = m0 + wid*16 + (lane >> 2);
    const int cb = (lane & 3)*2;
#pragma unroll
    for (int j = 0; j < 8; j++) {
        int c = c0 + j*8 + cb;
        float2 bz = *(const float2*)&g_bias1[c];
#pragma unroll
        for (int hrow = 0; hrow < 2; hrow++) {
            int m = r0 + hrow*8;
            float v0 = acc[j][hrow*2]   + bz.x;
            float v1 = acc[j][hrow*2+1] + bz.y;
            *(__half2*)&g_hioH[(size_t)m*512 + c] =
                __halves2half2(__float2half_rn(v0), __float2half_rn(v1));
        }
    }
}

// ---------------- GEMM2 (fp16x2): inp = A_adj @ hio + bias --------------------
// A split hi/lo (2 products), hio hi only.
#define G2_A   0          // 2 planes x 64 x 144 = 18432
#define G2_B   18432      // 1 plane  x 64 x 528 = 33792
#define G2_SMEM 52224

__global__ void __launch_bounds__(256, 2) gemm2_mma(const float* __restrict__ b_iah,
                                                    const float* __restrict__ b_oah) {
    extern __shared__ __align__(16) char smem[];
    const int t = threadIdx.x, wid = t >> 5, lane = t & 31;
    const int b = blockIdx.x, half_ = blockIdx.y;
    uint32_t sbase = smem_u32(smem);
    // load A: 2 planes x 64 rows x 8 segs
#pragma unroll
    for (int f = 0; f < 4; f++) {
        int u = f*256 + t; int pl = u >> 9, row = (u >> 3) & 63, seg = u & 7;
        const __half* src = pl ? g_AL : g_AH;
        cp16(sbase + G2_A + pl*9216 + row*144 + seg*16,
             src + (size_t)b*8192 + row*128 + half_*64 + seg*8);
    }
    // load hio tile (hi only): 64 rows x 32 segs
#pragma unroll
    for (int f = 0; f < 8; f++) {
        int u = f*256 + t; int row = u >> 5, seg = u & 31;
        cp16(sbase + G2_B + row*528 + seg*16,
             g_hioH + ((size_t)b*64 + row)*512 + half_*256 + seg*8);
    }
    CP_COMMIT(); CP_WAIT(0);
    __syncthreads();

    const int wr = wid >> 2, wc = wid & 3;
    float acc[2][8][4];
#pragma unroll
    for (int r = 0; r < 2; r++)
#pragma unroll
        for (int j = 0; j < 8; j++)
#pragma unroll
            for (int i = 0; i < 4; i++) acc[r][j][i] = 0.f;

    uint32_t aBase = sbase + G2_A + (wr*32 + (lane & 15))*144 + (lane >> 4)*16;
#pragma unroll
    for (int kt = 0; kt < 4; kt++) {
        uint32_t ah[2][4], al[2][4];
#pragma unroll
        for (int r = 0; r < 2; r++) {
            ldsm_x4(ah[r][0], ah[r][1], ah[r][2], ah[r][3],
                    aBase + r*2304 + kt*32);
            ldsm_x4(al[r][0], al[r][1], al[r][2], al[r][3],
                    aBase + 9216 + r*2304 + kt*32);
        }
#pragma unroll
        for (int jj = 0; jj < 4; jj++) {
            uint32_t ba = sbase + G2_B + (kt*16 + (lane & 15))*528 +
                          (wc*64 + jj*16 + (lane >> 4)*8)*2;
            uint32_t bh0, bh1, bh2, bh3;
            ldsm_x4_t(bh0, bh1, bh2, bh3, ba);
#pragma unroll
            for (int r = 0; r < 2; r++) {
                mma_f16(acc[r][jj*2],   ah[r][0], ah[r][1], ah[r][2], ah[r][3], bh0, bh1);
                mma_f16(acc[r][jj*2+1], ah[r][0], ah[r][1], ah[r][2], ah[r][3], bh2, bh3);
                mma_f16(acc[r][jj*2],   al[r][0], al[r][1], al[r][2], al[r][3], bh0, bh1);
                mma_f16(acc[r][jj*2+1], al[r][0], al[r][1], al[r][2], al[r][3], bh2, bh3);
            }
        }
    }
    const float* bias = half_ ? b_oah : b_iah;
#pragma unroll
    for (int r = 0; r < 2; r++) {
        int n = wr*32 + r*16 + (lane >> 2);
#pragma unroll
        for (int j = 0; j < 8; j++) {
            int col = wc*64 + j*8 + (lane & 3)*2;
#pragma unroll
            for (int hrow = 0; hrow < 2; hrow++) {
                int nn = n + hrow*8;
                float v0 = acc[r][j][hrow*2]   + bias[col];
                float v1 = acc[r][j][hrow*2+1] + bias[col+1];
                size_t o = ((size_t)b*64 + nn)*512 + half_*256 + col;
                *(__half2*)&g_inpH[o] =
                    __halves2half2(__float2half_rn(v0), __float2half_rn(v1));
            }
        }
    }
}

// ---------------- GEMM3: gates + fused GRU ------------------------------------
// CTA 128 rows x 32 cols x 4 planes. All chunks: A hi only.
#define G3_B     18432    // A hi
#define G3_STAGE 32256    // + B 96 x 144 = 13824
#define G3_BIAS  (2*G3_STAGE)
#define G3_SMEM  (G3_BIAS + 768)

__device__ __forceinline__ void g3_load(uint32_t sbase, int st, int ch,
                                        int m0, int c0) {
    const int t = threadIdx.x;
    uint32_t sb = sbase + st*G3_STAGE;
    const __half *Ah, *Bw; int ak, koff;
    if (ch < 8) { Ah = g_inpH; Bw = g_wih; ak = 512; koff = ch*64; }
    else        { Ah = g_hH;   Bw = g_whh; ak = 256; koff = (ch-8)*64; }
#pragma unroll
    for (int f = 0; f < 4; f++) {
        int u = f*256 + t; int row = u >> 3, seg = u & 7;
        cp16(sb + row*144 + seg*16,
             Ah + (size_t)(m0+row)*ak + koff + seg*8);
    }
#pragma unroll
    for (int f = 0; f < 3; f++) {
        int u = f*256 + t; int row = u >> 3, seg = u & 7;
        int g = row >> 5, n = row & 31;
        cp16(sb + G3_B + row*144 + seg*16,
             Bw + (size_t)(g*256 + c0 + n)*ak + koff + seg*8);
    }
}

template<bool GH>
__device__ __forceinline__ void g3_mma_chunk(uint32_t sb, int wr, int wc, int lane,
                                             float (&acc)[4][2][2][4]) {
    uint32_t aBase = sb + (wr*32 + (lane & 15))*144 + (lane >> 4)*16;
    const int midx = lane >> 3;
    const int trow = (midx >> 1)*8 + (lane & 7);
    const int kh   = (midx & 1)*16;
#pragma unroll
    for (int kt = 0; kt < 4; kt++) {
        uint32_t a[2][4];
#pragma unroll
        for (int r = 0; r < 2; r++)
            ldsm_x4(a[r][0], a[r][1], a[r][2], a[r][3],
                    aBase + r*2304 + kt*32);
#pragma unroll
        for (int g = 0; g < 3; g++) {
            const int p = (!GH || g < 2) ? g : 3;
            uint32_t b0, b1, b2, b3;
            ldsm_x4(b0, b1, b2, b3,
                    sb + G3_B + (g*32 + wc*16 + trow)*144 + kt*32 + kh);
#pragma unroll
            for (int r = 0; r < 2; r++) {
                mma_f16(acc[p][r][0], a[r][0], a[r][1], a[r][2], a[r][3], b0, b1);
                mma_f16(acc[p][r][1], a[r][0], a[r][1], a[r][2], a[r][3], b2, b3);
            }
        }
    }
}

__global__ void __launch_bounds__(256, 2) gemm3_mma(const float* __restrict__ b_ih,
                                                    const float* __restrict__ b_hh) {
    extern __shared__ __align__(16) char smem[];
    const int t = threadIdx.x, wid = t >> 5, lane = t & 31;
    const int c0 = blockIdx.x * 32, m0 = blockIdx.y * 128;
    const int wr = wid & 3, wc = wid >> 2;
    uint32_t sbase = smem_u32(smem);
    float* sbih = (float*)(smem + G3_BIAS);
    float* sbhh = (float*)(smem + G3_BIAS + 384);
    if (t < 32) {
#pragma unroll
        for (int g = 0; g < 3; g++) {
            sbih[g*32 + t] = b_ih[g*256 + c0 + t];
            sbhh[g*32 + t] = b_hh[g*256 + c0 + t];
        }
    }
    float acc[4][2][2][4];
#pragma unroll
    for (int p = 0; p < 4; p++)
#pragma unroll
        for (int r = 0; r < 2; r++)
#pragma unroll
            for (int cgi = 0; cgi < 2; cgi++)
#pragma unroll
                for (int i = 0; i < 4; i++) acc[p][r][cgi][i] = 0.f;

    g3_load(sbase, 0, 0, m0, c0);
    CP_COMMIT();

    for (int ch = 0; ch < 12; ch++) {
        if (ch + 1 < 12) {
            g3_load(sbase, (ch + 1) & 1, ch + 1, m0, c0);
            CP_COMMIT();
            CP_WAIT(1);
        } else {
            CP_WAIT(0);
        }
        __syncthreads();
        uint32_t sb = sbase + (ch & 1)*G3_STAGE;
        if (ch < 8) g3_mma_chunk<false>(sb, wr, wc, lane, acc);
        else        g3_mma_chunk<true >(sb, wr, wc, lane, acc);
        __syncthreads();
    }

    // GRU epilogue (h reconstructed exactly from fp16 hi/lo pair)
    const int rbase = m0 + wr*32 + (lane >> 2);
    const int cb = (lane & 3)*2;
#pragma unroll
    for (int r = 0; r < 2; r++) {
#pragma unroll
        for (int cgi = 0; cgi < 2; cgi++) {
            int cl = wc*16 + cgi*8 + cb;
            int c  = c0 + cl;
#pragma unroll
            for (int hrow = 0; hrow < 2; hrow++) {
                int m = rbase + r*16 + hrow*8;
                __half2 hh = *(const __half2*)&g_hH[(size_t)m*256 + c];
                __half2 hl = *(const __half2*)&g_hL[(size_t)m*256 + c];
                float hv[2];
                hv[0] = __half2float(__low2half(hh)) + __half2float(__low2half(hl));
                hv[1] = __half2float(__high2half(hh)) + __half2float(__high2half(hl));
                float o[2];
#pragma unroll
                for (int e = 0; e < 2; e++) {
                    int li = cl + e;
                    int fi = hrow*2 + e;
                    float rr = 1.f/(1.f + expf(-(acc[0][r][cgi][fi] +
                                                 sbih[li] + sbhh[li])));
                    float zz = 1.f/(1.f + expf(-(acc[1][r][cgi][fi] +
                                                 sbih[32+li] + sbhh[32+li])));
                    float nn = tanhf(acc[2][r][cgi][fi] + sbih[64+li] +
                                     rr*(acc[3][r][cgi][fi] + sbhh[64+li]));
                    o[e] = nn + zz*(hv[e] - nn);
                }
                *(float2*)&g_hn[(size_t)m*256 + c] = make_float2(o[0], o[1]);
            }
        }
    }
}

// ---------------- attention / star update (hn cached in smem) -----------------
#define ATTN_SMEM ((16384 + 256 + 64 + 64 + 64) * 4)

__global__ void __launch_bounds__(256) attn(const float* __restrict__ mask,
                                            float* __restrict__ out,
                                            int final_) {
    extern __shared__ float sm[];
    float* s_hn    = sm;              // 64 x 256
    float* s_star  = sm + 16384;
    float* s_alpha = s_star + 256;
    float* s_v     = s_alpha + 64;
    float* s_p     = s_v + 64;
    int b = blockIdx.x, t = threadIdx.x, lane = t & 31, w = t >> 5;
    s_star[t] = g_star[(size_t)b*256 + t];
    const float4* src = (const float4*)&g_hn[(size_t)b*64*256];
    float4* dst = (float4*)s_hn;
#pragma unroll
    for (int f = 0; f < 16; f++) dst[f*256 + t] = src[f*256 + t];
    __syncthreads();
#pragma unroll
    for (int r = 0; r < 8; r++) {
        int n = w*8 + r;
        float p = 0.f;
#pragma unroll
        for (int j = lane; j < 256; j += 32) p += s_hn[n*256 + j] * s_star[j];
#pragma unroll
        for (int o = 16; o; o >>= 1) p += __shfl_xor_sync(0xffffffffu, p, o);
        if (lane == 0) s_v[n] = p;
    }
    __syncthreads();
    float ss = 0.f;
#pragma unroll 8
    for (int j = 0; j < 256; j++) { float x = s_star[j]; ss += x*x; }
    if (t < 64) {
        float sraw = s_v[t];
        float a = 1.f / (1.f + expf(-sraw * 0.0625f));
        s_alpha[t] = a;
        float d2 = (1.f - a)*sraw + a*ss;
        s_v[t] = expf(d2) * mask[(size_t)b*64 + t];
    }
    __syncthreads();
    float den = 1e-24f;
#pragma unroll
    for (int n = 0; n < 64; n++) den += s_v[n];
    if (t < 64) s_p[t] = s_v[t] / den;
    __syncthreads();
    float st = s_star[t];
    float accS = 0.f;
#pragma unroll 4
    for (int n = 0; n < 64; n++) {
        float a = s_alpha[n];
        size_t idx = ((size_t)b*64 + n)*256 + t;
        float h2 = (1.f - a)*s_hn[n*256 + t] + a*st;
        __half hi, lo; h_split(h2, hi, lo);
        g_hH[idx] = hi; g_hL[idx] = lo;
        if (final_) out[idx] = h2;
        accS += s_p[n] * h2;
    }
    g_star[(size_t)b*256 + t] = accS;
    if (final_) out[(size_t)Bb*Nn*Hh + (size_t)b*256 + t] = accS;
}

// ---------------- launch ------------------------------------------------------
extern "C" void kernel_launch(void* const* d_in, const int* in_sizes, int n_in,
                              void* d_out, int out_size) {
    const float* A      = (const float*)d_in[0];
    const float* hidden = (const float*)d_in[1];
    const float* mask   = (const float*)d_in[2];
    const float* w_ih   = (const float*)d_in[3];
    const float* w_hh   = (const float*)d_in[4];
    const float* b_ih   = (const float*)d_in[5];
    const float* b_hh   = (const float*)d_in[6];
    const float* b_iah  = (const float*)d_in[7];
    const float* b_oah  = (const float*)d_in[8];
    const float* W_in   = (const float*)d_in[9];
    const float* b_in   = (const float*)d_in[10];
    const float* W_out  = (const float*)d_in[11];
    const float* b_out  = (const float*)d_in[12];
    float* out = (float*)d_out;

    cudaFuncSetAttribute(gemm1_mma, cudaFuncAttributeMaxDynamicSharedMemorySize, G1_SMEM);
    cudaFuncSetAttribute(gemm2_mma, cudaFuncAttributeMaxDynamicSharedMemorySize, G2_SMEM);
    cudaFuncSetAttribute(gemm3_mma, cudaFuncAttributeMaxDynamicSharedMemorySize, G3_SMEM);
    cudaFuncSetAttribute(attn,      cudaFuncAttributeMaxDynamicSharedMemorySize, ATTN_SMEM);

    setup_weights<<<1536, 256>>>(W_in, b_in, W_out, b_out, w_ih, w_hh);
    setup_A<<<4096, 256>>>(A);
    init_h<<<Bb, 256>>>(hidden, mask);

    for (int s = 0; s < 2; s++) {
        gemm1_mma<<<dim3(8, 1024), 256, G1_SMEM>>>();
        gemm2_mma<<<dim3(Bb, 2), 256, G2_SMEM>>>(b_iah, b_oah);
        gemm3_mma<<<dim3(8, 1024), 256, G3_SMEM>>>(b_ih, b_hh);
        attn<<<Bb, 256, ATTN_SMEM>>>(mask, out, s == 1);
    }
}